// round 7
// baseline (speedup 1.0000x reference)
#include <cuda_runtime.h>
#include <cuda_bf16.h>
#include <math.h>

#define HW   16384
#define B_   4

// ---------------- scratch ------------------------------------------------------
__device__ float g_xbuf0[B_*64*HW];
__device__ float g_xbuf1[B_*64*HW];
__device__ float g_off  [B_*18*HW];
__device__ float g_mask [B_*9*HW];
__device__ float g_xfin [B_*3*HW];
__device__ float g_ch   [B_*16*27];
__device__ float g_pool [B_*3];
__device__ __align__(16) __nv_bfloat16 g_whi[3*64*640];
__device__ __align__(16) __nv_bfloat16 g_wlo[3*64*640];

__device__ __forceinline__ float sigm(float v){ return 1.f/(1.f+__expf(-v)); }

// ---- packed fp32x2 helpers ----------------------------------------------------
typedef unsigned long long ull;
__device__ __forceinline__ ull dup2(float v){
    ull r; asm("mov.b64 %0, {%1, %1};" : "=l"(r) : "f"(v)); return r;
}
__device__ __forceinline__ void ffma2(ull &d, ull a, ull b){
    asm("fma.rn.f32x2 %0, %1, %2, %0;" : "+l"(d) : "l"(a), "l"(b));
}
__device__ __forceinline__ float2 unpk(ull v){
    float2 f; asm("mov.b64 {%0, %1}, %2;" : "=f"(f.x), "=f"(f.y) : "l"(v)); return f;
}

// ---- warp-level bf16 MMA (sm_80+ PTX, assembles for compute_103) -------------
__device__ __forceinline__ void mma16816(float* d, const unsigned* a, const unsigned* bb){
    asm volatile(
        "mma.sync.aligned.m16n8k16.row.col.f32.bf16.bf16.f32 "
        "{%0,%1,%2,%3}, {%4,%5,%6,%7}, {%8,%9}, {%0,%1,%2,%3};"
        : "+f"(d[0]), "+f"(d[1]), "+f"(d[2]), "+f"(d[3])
        : "r"(a[0]), "r"(a[1]), "r"(a[2]), "r"(a[3]), "r"(bb[0]), "r"(bb[1]));
}

// ---------------- 1) ConvLSTM --------------------------------------------------
__global__ void lstm_kernel(const float* __restrict__ X, const float* __restrict__ w,
                            const float* __restrict__ bias,
                            float* __restrict__ hid, float* __restrict__ cell)
{
    int idx = blockIdx.x*256 + threadIdx.x;
    int x = idx & 127, y = (idx >> 7) & 127, k = (idx >> 14) & 63, b = idx >> 20;
    float ai = bias[k], ao = bias[128+k], ag = bias[192+k];
    const float* Xb = X + b*3*HW;
    const float* wi = w + k*603;
    const float* wo = w + (128+k)*603;
    const float* wg = w + (192+k)*603;
    #pragma unroll
    for (int c = 0; c < 3; c++)
        #pragma unroll
        for (int dy = 0; dy < 3; dy++) {
            int yy = y + dy - 1;
            #pragma unroll
            for (int dx = 0; dx < 3; dx++) {
                int xx = x + dx - 1;
                float v = (yy >= 0 && yy < 128 && xx >= 0 && xx < 128)
                        ? Xb[c*HW + yy*128 + xx] : 0.f;
                int t = c*9 + dy*3 + dx;
                ai = fmaf(wi[t], v, ai);
                ao = fmaf(wo[t], v, ao);
                ag = fmaf(wg[t], v, ag);
            }
        }
    float cc = sigm(ai)*tanhf(ag);
    float hh = sigm(ao)*tanhf(cc);
    hid[idx]  = hh;
    cell[idx] = cc;
}

// ---------------- 2) offset/mask conv, f32x2 packed GEMM ----------------------
__global__ __launch_bounds__(256) void conv_off_kernel(
    const float* __restrict__ xin, const float* __restrict__ lr,
    const float* __restrict__ w0, const float* __restrict__ b0,
    const float* __restrict__ w1, const float* __restrict__ b1,
    float* __restrict__ out0, float* __restrict__ out1)
{
    __shared__ float sTile[16*3*132];
    __shared__ float sW[144*32];

    int tid = threadIdx.x;
    int pg = tid & 31;
    int og = tid >> 5;
    int b = blockIdx.y, y = blockIdx.x;
    int y0 = y - 1;

    ull acc[2][4];
    #pragma unroll
    for (int q = 0; q < 2; q++)
        #pragma unroll
        for (int p = 0; p < 4; p++) acc[q][p] = 0ull;

    for (int c0 = 0; c0 < 67; c0 += 16) {
        int cnt = (67 - c0) < 16 ? (67 - c0) : 16;
        for (int i = tid; i < cnt*396; i += 256) {
            int c = i / 396, rem = i - c*396;
            int r = rem / 132, col = rem - r*132;
            int gy = y0 + r, gx = col - 1;
            int cg = c0 + c;
            const float* src = (cg < 64) ? (xin + (b*64 + cg)*HW)
                                         : (lr  + (b*3 + (cg-64))*HW);
            sTile[i] = (gx >= 0 && gx < 128 && gy >= 0 && gy < 128)
                     ? src[gy*128 + gx] : 0.f;
        }
        int c09 = c0*9;
        for (int i = tid; i < cnt*288; i += 256) {
            int o = i & 31, tdx = i >> 5;
            float wv = 0.f;
            if (o < 18)      wv = w0[o*603 + c09 + tdx];
            else if (o < 27) wv = w1[(o-18)*603 + c09 + tdx];
            sW[tdx*32 + o] = wv;
        }
        __syncthreads();

        for (int c = 0; c < cnt; c++) {
            #pragma unroll
            for (int ky = 0; ky < 3; ky++) {
                const float* rb = sTile + c*396 + ky*132 + pg*4;
                float4 a4 = *(const float4*)rb;
                float2 a2 = *(const float2*)(rb + 4);
                ull vv[6];
                vv[0] = dup2(a4.x); vv[1] = dup2(a4.y); vv[2] = dup2(a4.z);
                vv[3] = dup2(a4.w); vv[4] = dup2(a2.x); vv[5] = dup2(a2.y);
                #pragma unroll
                for (int kx = 0; kx < 3; kx++) {
                    ulonglong2 w = *(const ulonglong2*)(sW + (c*9 + ky*3 + kx)*32 + og*4);
                    #pragma unroll
                    for (int p = 0; p < 4; p++) {
                        ffma2(acc[0][p], w.x, vv[kx + p]);
                        ffma2(acc[1][p], w.y, vv[kx + p]);
                    }
                }
            }
        }
        __syncthreads();
    }

    int pixb = y*128 + pg*4;
    #pragma unroll
    for (int wp = 0; wp < 2; wp++) {
        int o0 = og*4 + 2*wp;
        float2 a0 = unpk(acc[wp][0]), a1 = unpk(acc[wp][1]);
        float2 a2 = unpk(acc[wp][2]), a3 = unpk(acc[wp][3]);
        if (o0 < 18) {
            float bb = b0[o0];
            *(float4*)(out0 + (b*18 + o0)*HW + pixb) =
                make_float4(a0.x+bb, a1.x+bb, a2.x+bb, a3.x+bb);
        } else if (o0 < 27) {
            float bb = b1[o0-18];
            *(float4*)(out1 + (b*9 + (o0-18))*HW + pixb) =
                make_float4(2.f*sigm(a0.x+bb), 2.f*sigm(a1.x+bb),
                            2.f*sigm(a2.x+bb), 2.f*sigm(a3.x+bb));
        }
        int o1 = o0 + 1;
        if (o1 < 18) {
            float bb = b0[o1];
            *(float4*)(out0 + (b*18 + o1)*HW + pixb) =
                make_float4(a0.y+bb, a1.y+bb, a2.y+bb, a3.y+bb);
        } else if (o1 < 27) {
            float bb = b1[o1-18];
            *(float4*)(out1 + (b*9 + (o1-18))*HW + pixb) =
                make_float4(2.f*sigm(a0.y+bb), 2.f*sigm(a1.y+bb),
                            2.f*sigm(a2.y+bb), 2.f*sigm(a3.y+bb));
        }
    }
}

// ---------------- 2b) small direct conv ---------------------------------------
template<int COUT>
__global__ __launch_bounds__(256) void conv_small_kernel(
    const float* __restrict__ xin, const float* __restrict__ lr,
    const float* __restrict__ w0, const float* __restrict__ b0,
    float* __restrict__ out0)
{
    __shared__ float sT[16*10*34];
    __shared__ float sW[COUT*16*9];
    int tid = threadIdx.x;
    int tx = tid & 31, ty = tid >> 5;
    int b = blockIdx.z;
    int x = blockIdx.x*32 + tx, y = blockIdx.y*8 + ty;
    int gx0 = blockIdx.x*32 - 1, gy0 = blockIdx.y*8 - 1;

    float acc[COUT];
    #pragma unroll
    for (int o = 0; o < COUT; o++) acc[o] = 0.f;

    for (int c0 = 0; c0 < 67; c0 += 16) {
        int cnt = (67 - c0) < 16 ? (67 - c0) : 16;
        for (int i = tid; i < cnt*340; i += 256) {
            int c = i / 340, rem = i - c*340;
            int r = rem / 34, col = rem - r*34;
            int gy = gy0 + r, gx = gx0 + col;
            int cg = c0 + c;
            const float* src = (cg < 64) ? (xin + (b*64 + cg)*HW)
                                         : (lr  + (b*3 + (cg-64))*HW);
            sT[i] = (gy >= 0 && gy < 128 && gx >= 0 && gx < 128)
                  ? src[gy*128 + gx] : 0.f;
        }
        int wtot = COUT*cnt*9;
        for (int i = tid; i < wtot; i += 256) {
            int o = i / (cnt*9), rem = i - o*(cnt*9);
            sW[o*144 + rem] = w0[o*603 + c0*9 + rem];
        }
        __syncthreads();
        for (int c = 0; c < cnt; c++) {
            float win[9];
            #pragma unroll
            for (int r = 0; r < 3; r++)
                #pragma unroll
                for (int q = 0; q < 3; q++)
                    win[r*3+q] = sT[c*340 + (ty+r)*34 + (tx+q)];
            #pragma unroll
            for (int o = 0; o < COUT; o++) {
                #pragma unroll
                for (int t = 0; t < 9; t++)
                    acc[o] = fmaf(sW[o*144 + c*9 + t], win[t], acc[o]);
            }
        }
        __syncthreads();
    }
    int pix = y*128 + x;
    #pragma unroll
    for (int o = 0; o < COUT; o++)
        out0[(b*COUT + o)*HW + pix] = acc[o] + b0[o];
}

// ---------------- prep: bf16 hi/lo split of the 3 deform GEMM weights ---------
__global__ void wsplit_kernel(const float* __restrict__ w1,
                              const float* __restrict__ w2,
                              const float* __restrict__ w3)
{
    int idx = blockIdx.x*256 + threadIdx.x;          // 3*64*640
    if (idx >= 3*64*640) return;
    int s = idx / 40960, rem = idx - s*40960;
    int o = rem / 640, j = rem - o*640;
    const float* w = (s == 0) ? w1 : (s == 1) ? w2 : w3;
    float v = (j < 603) ? w[o*603 + j] : 0.f;
    __nv_bfloat16 h = __float2bfloat16(v);
    g_whi[idx] = h;
    g_wlo[idx] = __float2bfloat16(v - __bfloat162float(h));
}

// ---------------- 3) deform: gather + HMMA bf16 split-MMA ---------------------
// D[128 px][64 out] = V[128][640] * W[64][640]^T  (hi/lo splits, 3 passes)
// smem bytes: AHI 18432 | ALO 18432 | BHI 9216 | BLO 9216 | SWT 18432 | SIDX 4608
// A/B padded to stride 72 halves (144B) -> conflict-free fragment loads.
// sD (64*132 f32 = 33792B) overlays AHI+ALO after the MMA loop.
#define DM_AHI   0
#define DM_ALO   18432
#define DM_BHI   36864
#define DM_BLO   46080
#define DM_SWT   55296
#define DM_SIDX  73728
#define DM_SMEM  78336

__global__ __launch_bounds__(256, 2) void deform_mma_kernel(
    const float* __restrict__ xin, const float* __restrict__ lr,
    const __nv_bfloat16* __restrict__ whi, const __nv_bfloat16* __restrict__ wlo,
    const float* __restrict__ bias, float* __restrict__ out)
{
    extern __shared__ char sm[];
    char* base = sm;
    float4* sWt = (float4*)(base + DM_SWT);
    int*    sIdx = (int*)(base + DM_SIDX);

    int tid = threadIdx.x, warp = tid >> 5, lane = tid & 31;
    int b = blockIdx.y, y = blockIdx.x;

    // ---- Phase A: bilinear meta (9 taps x 128 px) ----
    for (int e = tid; e < 1152; e += 256) {
        int p = e & 127, k = e >> 7;
        int pix = y*128 + p;
        float offy = g_off [(b*18 + 2*k    )*HW + pix];
        float offx = g_off [(b*18 + 2*k + 1)*HW + pix];
        float m    = g_mask[(b*9  + k      )*HW + pix];
        int ky = k / 3, kx = k - ky*3;
        float py = (float)(y + ky - 1) + offy;
        float px = (float)(p + kx - 1) + offx;
        float fy = floorf(py), fx = floorf(px);
        float wy = py - fy,    wx = px - fx;
        int iy = (int)fy, ix = (int)fx;
        bool vy0 = (iy   >= 0 && iy   <= 127);
        bool vy1 = (iy+1 >= 0 && iy+1 <= 127);
        bool vx0 = (ix   >= 0 && ix   <= 127);
        bool vx1 = (ix+1 >= 0 && ix+1 <= 127);
        float4 wv;
        wv.x = (1.f-wy)*(1.f-wx)*m * ((vy0 && vx0) ? 1.f : 0.f);
        wv.y = (1.f-wy)*wx      *m * ((vy0 && vx1) ? 1.f : 0.f);
        wv.z = wy*(1.f-wx)      *m * ((vy1 && vx0) ? 1.f : 0.f);
        wv.w = wy*wx            *m * ((vy1 && vx1) ? 1.f : 0.f);
        sWt[e] = wv;
        int iy0 = min(max(iy,   0), 127), iy1 = min(max(iy+1, 0), 127);
        int ix0 = min(max(ix,   0), 127), ix1 = min(max(ix+1, 0), 127);
        sIdx[e] = iy0 | (iy1 << 8) | (ix0 << 16) | (ix1 << 24);
    }
    __syncthreads();

    const float* xb = xin + b*64*HW;
    const float* lb = lr  + b*3*HW;

    float acc[8][4];
    #pragma unroll
    for (int nt = 0; nt < 8; nt++)
        #pragma unroll
        for (int q = 0; q < 4; q++) acc[nt][q] = 0.f;

    int prow = warp*16;                       // this warp's 16 px rows
    int arow = prow + (lane >> 2);            // fragment row within A
    int acol4 = (lane & 3)*4;                 // byte offset of the half-pair

    for (int c = 0; c < 10; c++) {
        // ---- stage B chunk (hi+lo): 64 outs x 64 halves, stride 144B ----
        // 2 splits x 64 rows x 32 words = 4096 words
        for (int i = tid; i < 4096; i += 256) {
            int sp = i >> 11, r = i & 2047;
            int o = r >> 5, w = r & 31;
            const char* src = (const char*)(sp ? wlo : whi) + o*1280 + c*128 + w*4;
            *(unsigned*)(base + (sp ? DM_BLO : DM_BHI) + o*144 + w*4) =
                *(const unsigned*)src;
        }
        // ---- gather A chunk: 128 px x 64 k, hi/lo bf16x2 stores ----
        for (int e = tid; e < 4096; e += 256) {
            int px = e >> 5, jj = e & 31;
            float v[2];
            #pragma unroll
            for (int t = 0; t < 2; t++) {
                int kk = c*64 + jj*2 + t;
                float val = 0.f;
                if (kk < 603) {
                    int cc = kk / 9, k = kk - cc*9;
                    int mi = (k << 7) | px;
                    float4 wt = sWt[mi];
                    int pk = sIdx[mi];
                    int iy0 =  pk        & 255, iy1 = (pk >> 8)  & 255;
                    int ix0 = (pk >> 16) & 255, ix1 = (pk >> 24) & 255;
                    const float* src = (cc < 64) ? (xb + cc*HW) : (lb + (cc-64)*HW);
                    val = wt.x * __ldg(src + iy0*128 + ix0)
                        + wt.y * __ldg(src + iy0*128 + ix1)
                        + wt.z * __ldg(src + iy1*128 + ix0)
                        + wt.w * __ldg(src + iy1*128 + ix1);
                }
                v[t] = val;
            }
            __nv_bfloat16 h0 = __float2bfloat16(v[0]);
            __nv_bfloat16 h1 = __float2bfloat16(v[1]);
            __nv_bfloat162 hh; hh.x = h0; hh.y = h1;
            __nv_bfloat162 ll;
            ll.x = __float2bfloat16(v[0] - __bfloat162float(h0));
            ll.y = __float2bfloat16(v[1] - __bfloat162float(h1));
            *(unsigned*)(base + DM_AHI + px*144 + jj*4) = *(unsigned*)&hh;
            *(unsigned*)(base + DM_ALO + px*144 + jj*4) = *(unsigned*)&ll;
        }
        __syncthreads();

        // ---- MMA: 4 k-steps x 8 n-tiles x 3 passes ----
        #pragma unroll
        for (int ks = 0; ks < 4; ks++) {
            int k0b = ks*32;                          // k-step byte offset (16 halves)
            unsigned ahi[4], alo[4];
            {
                const char* a0 = base + arow*144 + k0b + acol4;
                ahi[0] = *(const unsigned*)(a0 + DM_AHI);
                ahi[1] = *(const unsigned*)(a0 + DM_AHI + 8*144);
                ahi[2] = *(const unsigned*)(a0 + DM_AHI + 16);
                ahi[3] = *(const unsigned*)(a0 + DM_AHI + 8*144 + 16);
                alo[0] = *(const unsigned*)(a0 + DM_ALO);
                alo[1] = *(const unsigned*)(a0 + DM_ALO + 8*144);
                alo[2] = *(const unsigned*)(a0 + DM_ALO + 16);
                alo[3] = *(const unsigned*)(a0 + DM_ALO + 8*144 + 16);
            }
            #pragma unroll
            for (int nt = 0; nt < 8; nt++) {
                int n = nt*8 + (lane >> 2);
                const char* bsrc = base + n*144 + k0b + acol4;
                unsigned bhi[2], blo[2];
                bhi[0] = *(const unsigned*)(bsrc + DM_BHI);
                bhi[1] = *(const unsigned*)(bsrc + DM_BHI + 16);
                blo[0] = *(const unsigned*)(bsrc + DM_BLO);
                blo[1] = *(const unsigned*)(bsrc + DM_BLO + 16);
                mma16816(acc[nt], ahi, bhi);
                mma16816(acc[nt], ahi, blo);
                mma16816(acc[nt], alo, bhi);
            }
        }
        __syncthreads();
    }

    // ---- epilogue: stage D to smem (overlay A region), coalesced store ----
    float* sD = (float*)(base + DM_AHI);            // [64 out][132 px]
    #pragma unroll
    for (int nt = 0; nt < 8; nt++) {
        int o = nt*8 + (lane & 3)*2;
        int p0 = prow + (lane >> 2);
        sD[o*132 + p0]       = acc[nt][0];
        sD[(o+1)*132 + p0]   = acc[nt][1];
        sD[o*132 + p0+8]     = acc[nt][2];
        sD[(o+1)*132 + p0+8] = acc[nt][3];
    }
    __syncthreads();
    float* ob = out + b*64*HW + y*128;
    for (int i = tid; i < 2048; i += 256) {         // 64 outs x 32 float4
        int o = i >> 5, w = i & 31;
        float4 v = *(const float4*)(sD + o*132 + w*4);
        float bb = bias[o];
        v.x += bb; v.y += bb; v.z += bb; v.w += bb;
        *(float4*)(ob + o*HW + w*4) = v;
    }
}

// ---------------- 4) global average pool --------------------------------------
__global__ void pool_kernel(const float* __restrict__ xf)
{
    __shared__ float red[256];
    int bc = blockIdx.x, tid = threadIdx.x;
    float s = 0.f;
    const float* p = xf + bc*HW;
    for (int i = tid; i < HW; i += 256) s += p[i];
    red[tid] = s; __syncthreads();
    for (int st = 128; st > 0; st >>= 1) {
        if (tid < st) red[tid] += red[tid + st];
        __syncthreads();
    }
    if (tid == 0) g_pool[bc] = red[0] * (1.f/HW);
}

// ---------------- 5) channel-filter MLP ---------------------------------------
__global__ void ch_kernel(const float* __restrict__ ch_w1, const float* __restrict__ ch_b1,
                          const float* __restrict__ ch_w2, const float* __restrict__ ch_b2)
{
    int t = threadIdx.x;
    if (t >= 64) return;
    int b = t >> 4, s = t & 15;
    float h1[4];
    #pragma unroll
    for (int m = 0; m < 4; m++) {
        float a = ch_b1[s*4 + m];
        #pragma unroll
        for (int c = 0; c < 3; c++) a = fmaf(g_pool[b*3 + c], ch_w1[(s*4 + m)*3 + c], a);
        h1[m] = fmaxf(a, 0.f);
    }
    for (int k = 0; k < 27; k++) {
        float a = ch_b2[s*27 + k];
        #pragma unroll
        for (int m = 0; m < 4; m++) a = fmaf(h1[m], ch_w2[(s*27 + k)*4 + m], a);
        g_ch[(b*16 + s)*27 + k] = a;
    }
}

// ---------------- 6) DDF up ----------------------------------------------------
__global__ __launch_bounds__(256) void ddf_kernel(
    const float* __restrict__ spw, const float* __restrict__ spb,
    float* __restrict__ out)
{
    __shared__ float sSpw[144*28];
    __shared__ float sSpb[144];
    __shared__ float sCh[432];
    int b = blockIdx.y, tid = threadIdx.x;
    for (int i = tid; i < 144*28; i += 256) {
        int row = i / 28, col = i - row*28;
        sSpw[i] = (col < 27) ? spw[row*27 + col] : 0.f;
    }
    if (tid < 144) sSpb[tid] = spb[tid];
    for (int i = tid; i < 432; i += 256) sCh[i] = g_ch[b*432 + i];
    __syncthreads();

    int pix = blockIdx.x*256 + tid;
    int x = pix & 127, y = pix >> 7;
    const float* xb = g_xfin + b*3*HW;

    float win[28];
    win[27] = 0.f;
    #pragma unroll
    for (int c = 0; c < 3; c++)
        #pragma unroll
        for (int r = 0; r < 3; r++) {
            int yy = y + r - 1;
            #pragma unroll
            for (int q = 0; q < 3; q++) {
                int xx = x + q - 1;
                win[c*9 + r*3 + q] = (yy >= 0 && yy < 128 && xx >= 0 && xx < 128)
                                   ? xb[c*HW + yy*128 + xx] : 0.f;
            }
        }

    float* ob = out + b*3*(512*512);
    #pragma unroll 1
    for (int s = 0; s < 16; s++) {
        float a0 = 0.f, a1 = 0.f, a2 = 0.f;
        #pragma unroll
        for (int k = 0; k < 9; k++) {
            float spv = sSpb[s*9 + k];
            const float4* w4 = (const float4*)(sSpw + (s*9 + k)*28);
            #pragma unroll
            for (int j4 = 0; j4 < 7; j4++) {
                float4 w = w4[j4];
                spv = fmaf(w.x, win[j4*4 + 0], spv);
                spv = fmaf(w.y, win[j4*4 + 1], spv);
                spv = fmaf(w.z, win[j4*4 + 2], spv);
                spv = fmaf(w.w, win[j4*4 + 3], spv);
            }
            a0 = fmaf(win[k],      sCh[s*27 + k]      + spv, a0);
            a1 = fmaf(win[9 + k],  sCh[s*27 + 9 + k]  + spv, a1);
            a2 = fmaf(win[18 + k], sCh[s*27 + 18 + k] + spv, a2);
        }
        int oy = (y << 2) + (s >> 2), ox = (x << 2) + (s & 3);
        ob[0*262144 + oy*512 + ox] = fminf(fmaxf(a0, 0.f), 255.f);
        ob[1*262144 + oy*512 + ox] = fminf(fmaxf(a1, 0.f), 255.f);
        ob[2*262144 + oy*512 + ox] = fminf(fmaxf(a2, 0.f), 255.f);
    }
}

// ---------------- host orchestration ------------------------------------------
extern "C" void kernel_launch(void* const* d_in, const int* in_sizes, int n_in,
                              void* d_out, int out_size)
{
    const float* X      = (const float*)d_in[0];
    const float* lstm_w = (const float*)d_in[1];
    const float* lstm_b = (const float*)d_in[2];
    const float* dw[3][6];
    for (int i = 0; i < 3; i++)
        for (int j = 0; j < 6; j++)
            dw[i][j] = (const float*)d_in[3 + i*6 + j];   // ow, ob, mw, mb, w, b
    const float* conv_w = (const float*)d_in[21];
    const float* conv_b = (const float*)d_in[22];
    const float* sp_w   = (const float*)d_in[23];
    const float* sp_b   = (const float*)d_in[24];
    const float* ch_w1  = (const float*)d_in[25];
    const float* ch_b1  = (const float*)d_in[26];
    const float* ch_w2  = (const float*)d_in[27];
    const float* ch_b2  = (const float*)d_in[28];

    float* out_main = (float*)d_out;                     // [4,3,512,512]
    float* hid      = out_main + 4*3*512*512;            // [4,64,128,128]
    float* cell     = hid + 4*64*128*128;                // [4,64,128,128]

    void *pxb0, *pxb1, *poff, *pmask, *pxfin, *pwhi, *pwlo;
    cudaGetSymbolAddress(&pxb0, g_xbuf0);
    cudaGetSymbolAddress(&pxb1, g_xbuf1);
    cudaGetSymbolAddress(&poff,  g_off);
    cudaGetSymbolAddress(&pmask, g_mask);
    cudaGetSymbolAddress(&pxfin, g_xfin);
    cudaGetSymbolAddress(&pwhi, g_whi);
    cudaGetSymbolAddress(&pwlo, g_wlo);
    float* xb0 = (float*)pxb0;
    float* xb1 = (float*)pxb1;
    float* off_p  = (float*)poff;
    float* mask_p = (float*)pmask;
    float* xfin_p = (float*)pxfin;
    const __nv_bfloat16* whi = (const __nv_bfloat16*)pwhi;
    const __nv_bfloat16* wlo = (const __nv_bfloat16*)pwlo;

    cudaFuncSetAttribute(deform_mma_kernel, cudaFuncAttributeMaxDynamicSharedMemorySize,
                         DM_SMEM);

    dim3 rowGrid(128, B_);
    dim3 convGrid(4, 16, B_);

    lstm_kernel<<<16384, 256>>>(X, lstm_w, lstm_b, hid, cell);
    wsplit_kernel<<<480, 256>>>(dw[0][4], dw[1][4], dw[2][4]);

    conv_off_kernel<<<rowGrid, 256>>>(hid, X, dw[0][0], dw[0][1],
                                      dw[0][2], dw[0][3], off_p, mask_p);
    deform_mma_kernel<<<rowGrid, 256, DM_SMEM>>>(hid, X, whi, wlo, dw[0][5], xb0);

    conv_off_kernel<<<rowGrid, 256>>>(xb0, X, dw[1][0], dw[1][1],
                                      dw[1][2], dw[1][3], off_p, mask_p);
    deform_mma_kernel<<<rowGrid, 256, DM_SMEM>>>(xb0, X, whi + 40960, wlo + 40960,
                                                 dw[1][5], xb1);

    conv_off_kernel<<<rowGrid, 256>>>(xb1, X, dw[2][0], dw[2][1],
                                      dw[2][2], dw[2][3], off_p, mask_p);
    deform_mma_kernel<<<rowGrid, 256, DM_SMEM>>>(xb1, X, whi + 81920, wlo + 81920,
                                                 dw[2][5], xb0);

    conv_small_kernel<3><<<convGrid, 256>>>(xb0, X, conv_w, conv_b, xfin_p);

    pool_kernel<<<B_*3, 256>>>(xfin_p);
    ch_kernel<<<1, 64>>>(ch_w1, ch_b1, ch_w2, ch_b2);
    ddf_kernel<<<dim3(64, B_), 256>>>(sp_w, sp_b, out_main);
}

// round 8
// speedup vs baseline: 1.8051x; 1.8051x over previous
#include <cuda_runtime.h>
#include <math.h>

#define HW   16384
#define B_   4

// ---------------- scratch ------------------------------------------------------
__device__ float g_xbuf0[B_*64*HW];
__device__ float g_xbuf1[B_*64*HW];
__device__ float g_off  [B_*18*HW];
__device__ float g_mask [B_*9*HW];
__device__ float g_xfin [B_*3*HW];
__device__ float g_ch   [B_*16*27];
__device__ float g_pool [B_*3];

__device__ __forceinline__ float sigm(float v){ return 1.f/(1.f+__expf(-v)); }

// ---- packed fp32x2 helpers ----------------------------------------------------
typedef unsigned long long ull;
__device__ __forceinline__ ull dup2(float v){
    ull r; asm("mov.b64 %0, {%1, %1};" : "=l"(r) : "f"(v)); return r;
}
__device__ __forceinline__ void ffma2(ull &d, ull a, ull b){
    asm("fma.rn.f32x2 %0, %1, %2, %0;" : "+l"(d) : "l"(a), "l"(b));
}
__device__ __forceinline__ float2 unpk(ull v){
    float2 f; asm("mov.b64 {%0, %1}, %2;" : "=f"(f.x), "=f"(f.y) : "l"(v)); return f;
}

// ---------------- 1) ConvLSTM (h=c=0 => only 3 input channels, no f gate) -----
__global__ void lstm_kernel(const float* __restrict__ X, const float* __restrict__ w,
                            const float* __restrict__ bias,
                            float* __restrict__ hid, float* __restrict__ cell)
{
    int idx = blockIdx.x*256 + threadIdx.x;
    int x = idx & 127, y = (idx >> 7) & 127, k = (idx >> 14) & 63, b = idx >> 20;
    float ai = bias[k], ao = bias[128+k], ag = bias[192+k];
    const float* Xb = X + b*3*HW;
    const float* wi = w + k*603;
    const float* wo = w + (128+k)*603;
    const float* wg = w + (192+k)*603;
    #pragma unroll
    for (int c = 0; c < 3; c++)
        #pragma unroll
        for (int dy = 0; dy < 3; dy++) {
            int yy = y + dy - 1;
            #pragma unroll
            for (int dx = 0; dx < 3; dx++) {
                int xx = x + dx - 1;
                float v = (yy >= 0 && yy < 128 && xx >= 0 && xx < 128)
                        ? Xb[c*HW + yy*128 + xx] : 0.f;
                int t = c*9 + dy*3 + dx;
                ai = fmaf(wi[t], v, ai);
                ao = fmaf(wo[t], v, ao);
                ag = fmaf(wg[t], v, ag);
            }
        }
    float cc = sigm(ai)*tanhf(ag);
    float hh = sigm(ao)*tanhf(cc);
    hid[idx]  = hh;
    cell[idx] = cc;
}

// ---------------- 2) offset/mask conv, f32x2 packed GEMM ----------------------
// Block = 256 threads, one full 128-px row. Thread tile: 4 outs (2 pairs) x 4 px.
__global__ __launch_bounds__(256) void conv_off_kernel(
    const float* __restrict__ xin, const float* __restrict__ lr,
    const float* __restrict__ w0, const float* __restrict__ b0,
    const float* __restrict__ w1, const float* __restrict__ b1,
    float* __restrict__ out0, float* __restrict__ out1)
{
    __shared__ float sTile[16*3*132];    // 16ch x 3 rows x 132 cols (col=gx+1)
    __shared__ float sW[144*32];

    int tid = threadIdx.x;
    int pg = tid & 31;
    int og = tid >> 5;
    int b = blockIdx.y, y = blockIdx.x;
    int y0 = y - 1;

    ull acc[2][4];
    #pragma unroll
    for (int q = 0; q < 2; q++)
        #pragma unroll
        for (int p = 0; p < 4; p++) acc[q][p] = 0ull;

    for (int c0 = 0; c0 < 67; c0 += 16) {
        int cnt = (67 - c0) < 16 ? (67 - c0) : 16;
        // zero the 4 edge cols of each staged row
        for (int i = tid; i < cnt*3; i += 256) {
            int c = i / 3, r = i - c*3;
            float* row = sTile + c*396 + r*132;
            row[0] = 0.f; row[129] = 0.f; row[130] = 0.f; row[131] = 0.f;
        }
        // main body: float4 coalesced loads, cols 1..128
        for (int i = tid; i < cnt*96; i += 256) {
            int c = i / 96, rem = i - c*96;
            int r = rem >> 5, q = rem & 31;
            int gy = y0 + r;
            int cg = c0 + c;
            const float* src = (cg < 64) ? (xin + (b*64 + cg)*HW)
                                         : (lr  + (b*3 + (cg-64))*HW);
            float4 v = make_float4(0.f, 0.f, 0.f, 0.f);
            if (gy >= 0 && gy < 128) v = *(const float4*)(src + gy*128 + q*4);
            float* dst = sTile + c*396 + r*132 + 1 + q*4;
            dst[0] = v.x; dst[1] = v.y; dst[2] = v.z; dst[3] = v.w;
        }
        // stage weights transposed
        int c09 = c0*9;
        for (int i = tid; i < cnt*288; i += 256) {
            int o = i & 31, tdx = i >> 5;
            float wv = 0.f;
            if (o < 18)      wv = w0[o*603 + c09 + tdx];
            else if (o < 27) wv = w1[(o-18)*603 + c09 + tdx];
            sW[tdx*32 + o] = wv;
        }
        __syncthreads();

        for (int c = 0; c < cnt; c++) {
            #pragma unroll
            for (int ky = 0; ky < 3; ky++) {
                const float* rb = sTile + c*396 + ky*132 + pg*4;
                float4 a4 = *(const float4*)rb;
                float2 a2 = *(const float2*)(rb + 4);
                ull vv[6];
                vv[0] = dup2(a4.x); vv[1] = dup2(a4.y); vv[2] = dup2(a4.z);
                vv[3] = dup2(a4.w); vv[4] = dup2(a2.x); vv[5] = dup2(a2.y);
                #pragma unroll
                for (int kx = 0; kx < 3; kx++) {
                    ulonglong2 w = *(const ulonglong2*)(sW + (c*9 + ky*3 + kx)*32 + og*4);
                    #pragma unroll
                    for (int p = 0; p < 4; p++) {
                        ffma2(acc[0][p], w.x, vv[kx + p]);
                        ffma2(acc[1][p], w.y, vv[kx + p]);
                    }
                }
            }
        }
        __syncthreads();
    }

    int pixb = y*128 + pg*4;
    #pragma unroll
    for (int wp = 0; wp < 2; wp++) {
        int o0 = og*4 + 2*wp;
        float2 a0 = unpk(acc[wp][0]), a1 = unpk(acc[wp][1]);
        float2 a2 = unpk(acc[wp][2]), a3 = unpk(acc[wp][3]);
        if (o0 < 18) {
            float bb = b0[o0];
            *(float4*)(out0 + (b*18 + o0)*HW + pixb) =
                make_float4(a0.x+bb, a1.x+bb, a2.x+bb, a3.x+bb);
        } else if (o0 < 27) {
            float bb = b1[o0-18];
            *(float4*)(out1 + (b*9 + (o0-18))*HW + pixb) =
                make_float4(2.f*sigm(a0.x+bb), 2.f*sigm(a1.x+bb),
                            2.f*sigm(a2.x+bb), 2.f*sigm(a3.x+bb));
        }
        int o1 = o0 + 1;
        if (o1 < 18) {
            float bb = b0[o1];
            *(float4*)(out0 + (b*18 + o1)*HW + pixb) =
                make_float4(a0.y+bb, a1.y+bb, a2.y+bb, a3.y+bb);
        } else if (o1 < 27) {
            float bb = b1[o1-18];
            *(float4*)(out1 + (b*9 + (o1-18))*HW + pixb) =
                make_float4(2.f*sigm(a0.y+bb), 2.f*sigm(a1.y+bb),
                            2.f*sigm(a2.y+bb), 2.f*sigm(a3.y+bb));
        }
    }
}

// ---------------- 2b) small direct conv (final 3-out fuse conv) ---------------
template<int COUT>
__global__ __launch_bounds__(256) void conv_small_kernel(
    const float* __restrict__ xin, const float* __restrict__ lr,
    const float* __restrict__ w0, const float* __restrict__ b0,
    float* __restrict__ out0)
{
    __shared__ float sT[16*10*34];
    __shared__ float sW[COUT*16*9];
    int tid = threadIdx.x;
    int tx = tid & 31, ty = tid >> 5;
    int b = blockIdx.z;
    int x = blockIdx.x*32 + tx, y = blockIdx.y*8 + ty;
    int gx0 = blockIdx.x*32 - 1, gy0 = blockIdx.y*8 - 1;

    float acc[COUT];
    #pragma unroll
    for (int o = 0; o < COUT; o++) acc[o] = 0.f;

    for (int c0 = 0; c0 < 67; c0 += 16) {
        int cnt = (67 - c0) < 16 ? (67 - c0) : 16;
        for (int i = tid; i < cnt*340; i += 256) {
            int c = i / 340, rem = i - c*340;
            int r = rem / 34, col = rem - r*34;
            int gy = gy0 + r, gx = gx0 + col;
            int cg = c0 + c;
            const float* src = (cg < 64) ? (xin + (b*64 + cg)*HW)
                                         : (lr  + (b*3 + (cg-64))*HW);
            sT[i] = (gy >= 0 && gy < 128 && gx >= 0 && gx < 128)
                  ? src[gy*128 + gx] : 0.f;
        }
        int wtot = COUT*cnt*9;
        for (int i = tid; i < wtot; i += 256) {
            int o = i / (cnt*9), rem = i - o*(cnt*9);
            sW[o*144 + rem] = w0[o*603 + c0*9 + rem];
        }
        __syncthreads();
        for (int c = 0; c < cnt; c++) {
            float win[9];
            #pragma unroll
            for (int r = 0; r < 3; r++)
                #pragma unroll
                for (int q = 0; q < 3; q++)
                    win[r*3+q] = sT[c*340 + (ty+r)*34 + (tx+q)];
            #pragma unroll
            for (int o = 0; o < COUT; o++) {
                #pragma unroll
                for (int t = 0; t < 9; t++)
                    acc[o] = fmaf(sW[o*144 + c*9 + t], win[t], acc[o]);
            }
        }
        __syncthreads();
    }
    int pix = y*128 + x;
    #pragma unroll
    for (int o = 0; o < COUT; o++)
        out0[(b*COUT + o)*HW + pix] = acc[o] + b0[o];
}

// ---------------- 3) deform: gather + 64x603 GEMM, f32x2, K-chunked -----------
// Block = 256 thr, one 128-px row. Thread tile: 8 outs (4 pairs) x 4 px.
// smem floats: sWt 1152*4 | sIdx 1152 | sV 67*132 | sWc 67*64  (75568 B -> 3 CTA/SM)
#define DF_SIDX  4608
#define DF_SV    (4608 + 1152)
#define DF_SWC   (DF_SV + 67*132)
#define DF_SMEM_BYTES ((DF_SWC + 67*64) * 4)

__global__ __launch_bounds__(256, 3) void deform_kernel(
    const float* __restrict__ xin, const float* __restrict__ lr,
    const float* __restrict__ wmain, const float* __restrict__ bias,
    float* __restrict__ out)
{
    extern __shared__ float smem[];
    float4* sWt = (float4*)smem;                 // [k][128 px] corner weights
    int*    sIdx= (int*)(smem + DF_SIDX);
    float*  sV  = smem + DF_SV;                  // [j][px], stride 132
    float*  sWc = smem + DF_SWC;                 // [j][64 outs]

    int tid = threadIdx.x;
    int b = blockIdx.y, y = blockIdx.x;

    // ---- Phase A: bilinear meta (9 taps x 128 px) ----
    for (int e = tid; e < 1152; e += 256) {
        int p = e & 127, k = e >> 7;
        int pix = y*128 + p;
        float offy = g_off [(b*18 + 2*k    )*HW + pix];
        float offx = g_off [(b*18 + 2*k + 1)*HW + pix];
        float m    = g_mask[(b*9  + k      )*HW + pix];
        int ky = k / 3, kx = k - ky*3;
        float py = (float)(y + ky - 1) + offy;
        float px = (float)(p + kx - 1) + offx;
        float fy = floorf(py), fx = floorf(px);
        float wy = py - fy,    wx = px - fx;
        int iy = (int)fy, ix = (int)fx;
        bool vy0 = (iy   >= 0 && iy   <= 127);
        bool vy1 = (iy+1 >= 0 && iy+1 <= 127);
        bool vx0 = (ix   >= 0 && ix   <= 127);
        bool vx1 = (ix+1 >= 0 && ix+1 <= 127);
        float4 wv;
        wv.x = (1.f-wy)*(1.f-wx)*m * ((vy0 && vx0) ? 1.f : 0.f);
        wv.y = (1.f-wy)*wx      *m * ((vy0 && vx1) ? 1.f : 0.f);
        wv.z = wy*(1.f-wx)      *m * ((vy1 && vx0) ? 1.f : 0.f);
        wv.w = wy*wx            *m * ((vy1 && vx1) ? 1.f : 0.f);
        sWt[e] = wv;
        int iy0 = min(max(iy,   0), 127), iy1 = min(max(iy+1, 0), 127);
        int ix0 = min(max(ix,   0), 127), ix1 = min(max(ix+1, 0), 127);
        sIdx[e] = iy0 | (iy1 << 8) | (ix0 << 16) | (ix1 << 24);
    }
    __syncthreads();

    const float* xb = xin + b*64*HW;
    const float* lb = lr  + b*3*HW;
    int pg = tid & 31, og = tid >> 5;

    ull acc[4][4];
    #pragma unroll
    for (int q = 0; q < 4; q++)
        #pragma unroll
        for (int p = 0; p < 4; p++) acc[q][p] = 0ull;

    for (int c0 = 0; c0 < 603; c0 += 67) {
        // stage weight chunk transposed
        for (int i = tid; i < 67*64; i += 256) {
            int o = i & 63, j = i >> 6;
            sWc[j*64 + o] = wmain[o*603 + c0 + j];
        }
        // gather V chunk [67][128]
        #pragma unroll 2
        for (int e = tid; e < 67*128; e += 256) {
            int p = e & 127, j = e >> 7;
            int kk = c0 + j;
            int c = kk / 9, k = kk - c*9;
            int mi = (k << 7) | p;
            float4 wt = sWt[mi];
            int pk = sIdx[mi];
            int iy0 =  pk        & 255, iy1 = (pk >> 8)  & 255;
            int ix0 = (pk >> 16) & 255, ix1 = (pk >> 24) & 255;
            const float* src = (c < 64) ? (xb + c*HW) : (lb + (c-64)*HW);
            float v = wt.x * __ldg(src + iy0*128 + ix0)
                    + wt.y * __ldg(src + iy0*128 + ix1)
                    + wt.z * __ldg(src + iy1*128 + ix0)
                    + wt.w * __ldg(src + iy1*128 + ix1);
            sV[j*132 + p] = v;
        }
        __syncthreads();

        const float* vp = sV + pg*4;
        const float* wp_ = sWc + og*8;
        #pragma unroll 4
        for (int j = 0; j < 67; j++) {
            ulonglong2 wA = *(const ulonglong2*)(wp_ + j*64);
            ulonglong2 wB = *(const ulonglong2*)(wp_ + j*64 + 4);
            float4 v = *(const float4*)(vp + j*132);
            ull v0 = dup2(v.x), v1 = dup2(v.y), v2 = dup2(v.z), v3 = dup2(v.w);
            ffma2(acc[0][0], wA.x, v0); ffma2(acc[0][1], wA.x, v1);
            ffma2(acc[0][2], wA.x, v2); ffma2(acc[0][3], wA.x, v3);
            ffma2(acc[1][0], wA.y, v0); ffma2(acc[1][1], wA.y, v1);
            ffma2(acc[1][2], wA.y, v2); ffma2(acc[1][3], wA.y, v3);
            ffma2(acc[2][0], wB.x, v0); ffma2(acc[2][1], wB.x, v1);
            ffma2(acc[2][2], wB.x, v2); ffma2(acc[2][3], wB.x, v3);
            ffma2(acc[3][0], wB.y, v0); ffma2(acc[3][1], wB.y, v1);
            ffma2(acc[3][2], wB.y, v2); ffma2(acc[3][3], wB.y, v3);
        }
        __syncthreads();
    }

    int pixb = y*128 + pg*4;
    #pragma unroll
    for (int wp = 0; wp < 4; wp++) {
        int o0 = og*8 + 2*wp;
        float2 a0 = unpk(acc[wp][0]), a1 = unpk(acc[wp][1]);
        float2 a2 = unpk(acc[wp][2]), a3 = unpk(acc[wp][3]);
        float bb0 = bias[o0], bb1 = bias[o0+1];
        *(float4*)(out + (b*64 + o0)*HW + pixb) =
            make_float4(a0.x+bb0, a1.x+bb0, a2.x+bb0, a3.x+bb0);
        *(float4*)(out + (b*64 + o0+1)*HW + pixb) =
            make_float4(a0.y+bb1, a1.y+bb1, a2.y+bb1, a3.y+bb1);
    }
}

// ---------------- 4) global average pool --------------------------------------
__global__ void pool_kernel(const float* __restrict__ xf)
{
    __shared__ float red[256];
    int bc = blockIdx.x, tid = threadIdx.x;
    float s = 0.f;
    const float* p = xf + bc*HW;
    for (int i = tid; i < HW; i += 256) s += p[i];
    red[tid] = s; __syncthreads();
    for (int st = 128; st > 0; st >>= 1) {
        if (tid < st) red[tid] += red[tid + st];
        __syncthreads();
    }
    if (tid == 0) g_pool[bc] = red[0] * (1.f/HW);
}

// ---------------- 5) channel-filter MLP ---------------------------------------
__global__ void ch_kernel(const float* __restrict__ ch_w1, const float* __restrict__ ch_b1,
                          const float* __restrict__ ch_w2, const float* __restrict__ ch_b2)
{
    int t = threadIdx.x;
    if (t >= 64) return;
    int b = t >> 4, s = t & 15;
    float h1[4];
    #pragma unroll
    for (int m = 0; m < 4; m++) {
        float a = ch_b1[s*4 + m];
        #pragma unroll
        for (int c = 0; c < 3; c++) a = fmaf(g_pool[b*3 + c], ch_w1[(s*4 + m)*3 + c], a);
        h1[m] = fmaxf(a, 0.f);
    }
    for (int k = 0; k < 27; k++) {
        float a = ch_b2[s*27 + k];
        #pragma unroll
        for (int m = 0; m < 4; m++) a = fmaf(h1[m], ch_w2[(s*27 + k)*4 + m], a);
        g_ch[(b*16 + s)*27 + k] = a;
    }
}

// ---------------- 6) DDF up ----------------------------------------------------
__global__ __launch_bounds__(256) void ddf_kernel(
    const float* __restrict__ spw, const float* __restrict__ spb,
    float* __restrict__ out)
{
    __shared__ float sSpw[144*28];
    __shared__ float sSpb[144];
    __shared__ float sCh[432];
    int b = blockIdx.y, tid = threadIdx.x;
    for (int i = tid; i < 144*28; i += 256) {
        int row = i / 28, col = i - row*28;
        sSpw[i] = (col < 27) ? spw[row*27 + col] : 0.f;
    }
    if (tid < 144) sSpb[tid] = spb[tid];
    for (int i = tid; i < 432; i += 256) sCh[i] = g_ch[b*432 + i];
    __syncthreads();

    int pix = blockIdx.x*256 + tid;
    int x = pix & 127, y = pix >> 7;
    const float* xb = g_xfin + b*3*HW;

    float win[28];
    win[27] = 0.f;
    #pragma unroll
    for (int c = 0; c < 3; c++)
        #pragma unroll
        for (int r = 0; r < 3; r++) {
            int yy = y + r - 1;
            #pragma unroll
            for (int q = 0; q < 3; q++) {
                int xx = x + q - 1;
                win[c*9 + r*3 + q] = (yy >= 0 && yy < 128 && xx >= 0 && xx < 128)
                                   ? xb[c*HW + yy*128 + xx] : 0.f;
            }
        }

    float* ob = out + b*3*(512*512);
    #pragma unroll 1
    for (int s = 0; s < 16; s++) {
        float a0 = 0.f, a1 = 0.f, a2 = 0.f;
        #pragma unroll
        for (int k = 0; k < 9; k++) {
            float spv = sSpb[s*9 + k];
            const float4* w4 = (const float4*)(sSpw + (s*9 + k)*28);
            #pragma unroll
            for (int j4 = 0; j4 < 7; j4++) {
                float4 w = w4[j4];
                spv = fmaf(w.x, win[j4*4 + 0], spv);
                spv = fmaf(w.y, win[j4*4 + 1], spv);
                spv = fmaf(w.z, win[j4*4 + 2], spv);
                spv = fmaf(w.w, win[j4*4 + 3], spv);
            }
            a0 = fmaf(win[k],      sCh[s*27 + k]      + spv, a0);
            a1 = fmaf(win[9 + k],  sCh[s*27 + 9 + k]  + spv, a1);
            a2 = fmaf(win[18 + k], sCh[s*27 + 18 + k] + spv, a2);
        }
        int oy = (y << 2) + (s >> 2), ox = (x << 2) + (s & 3);
        ob[0*262144 + oy*512 + ox] = fminf(fmaxf(a0, 0.f), 255.f);
        ob[1*262144 + oy*512 + ox] = fminf(fmaxf(a1, 0.f), 255.f);
        ob[2*262144 + oy*512 + ox] = fminf(fmaxf(a2, 0.f), 255.f);
    }
}

// ---------------- host orchestration ------------------------------------------
extern "C" void kernel_launch(void* const* d_in, const int* in_sizes, int n_in,
                              void* d_out, int out_size)
{
    const float* X      = (const float*)d_in[0];
    const float* lstm_w = (const float*)d_in[1];
    const float* lstm_b = (const float*)d_in[2];
    const float* dw[3][6];
    for (int i = 0; i < 3; i++)
        for (int j = 0; j < 6; j++)
            dw[i][j] = (const float*)d_in[3 + i*6 + j];   // ow, ob, mw, mb, w, b
    const float* conv_w = (const float*)d_in[21];
    const float* conv_b = (const float*)d_in[22];
    const float* sp_w   = (const float*)d_in[23];
    const float* sp_b   = (const float*)d_in[24];
    const float* ch_w1  = (const float*)d_in[25];
    const float* ch_b1  = (const float*)d_in[26];
    const float* ch_w2  = (const float*)d_in[27];
    const float* ch_b2  = (const float*)d_in[28];

    float* out_main = (float*)d_out;                     // [4,3,512,512]
    float* hid      = out_main + 4*3*512*512;            // [4,64,128,128]
    float* cell     = hid + 4*64*128*128;                // [4,64,128,128]

    void *pxb0, *pxb1, *poff, *pmask, *pxfin;
    cudaGetSymbolAddress(&pxb0, g_xbuf0);
    cudaGetSymbolAddress(&pxb1, g_xbuf1);
    cudaGetSymbolAddress(&poff,  g_off);
    cudaGetSymbolAddress(&pmask, g_mask);
    cudaGetSymbolAddress(&pxfin, g_xfin);
    float* xb0 = (float*)pxb0;
    float* xb1 = (float*)pxb1;
    float* off_p  = (float*)poff;
    float* mask_p = (float*)pmask;
    float* xfin_p = (float*)pxfin;

    cudaFuncSetAttribute(deform_kernel, cudaFuncAttributeMaxDynamicSharedMemorySize,
                         DF_SMEM_BYTES);

    dim3 rowGrid(128, B_);
    dim3 convGrid(4, 16, B_);

    lstm_kernel<<<16384, 256>>>(X, lstm_w, lstm_b, hid, cell);

    conv_off_kernel<<<rowGrid, 256>>>(hid, X, dw[0][0], dw[0][1],
                                      dw[0][2], dw[0][3], off_p, mask_p);
    deform_kernel<<<rowGrid, 256, DF_SMEM_BYTES>>>(hid, X, dw[0][4], dw[0][5], xb0);

    conv_off_kernel<<<rowGrid, 256>>>(xb0, X, dw[1][0], dw[1][1],
                                      dw[1][2], dw[1][3], off_p, mask_p);
    deform_kernel<<<rowGrid, 256, DF_SMEM_BYTES>>>(xb0, X, dw[1][4], dw[1][5], xb1);

    conv_off_kernel<<<rowGrid, 256>>>(xb1, X, dw[2][0], dw[2][1],
                                      dw[2][2], dw[2][3], off_p, mask_p);
    deform_kernel<<<rowGrid, 256, DF_SMEM_BYTES>>>(xb1, X, dw[2][4], dw[2][5], xb0);

    conv_small_kernel<3><<<convGrid, 256>>>(xb0, X, conv_w, conv_b, xfin_p);

    pool_kernel<<<B_*3, 256>>>(xfin_p);
    ch_kernel<<<1, 64>>>(ch_w1, ch_b1, ch_w2, ch_b2);
    ddf_kernel<<<dim3(64, B_), 256>>>(sp_w, sp_b, out_main);
}

// round 9
// speedup vs baseline: 1.8155x; 1.0058x over previous
#include <cuda_runtime.h>
#include <math.h>

#define HW   16384
#define B_   4

// ---------------- scratch ------------------------------------------------------
__device__ float g_xbuf0[B_*64*HW];
__device__ float g_xbuf1[B_*64*HW];
__device__ float g_off  [B_*18*HW];
__device__ float g_mask [B_*9*HW];
__device__ float g_xfin [B_*3*HW];
__device__ float g_ch   [B_*16*27];
__device__ float g_pool [B_*3];

__device__ __forceinline__ float sigm(float v){ return 1.f/(1.f+__expf(-v)); }

// ---- packed fp32x2 helpers ----------------------------------------------------
typedef unsigned long long ull;
__device__ __forceinline__ ull dup2(float v){
    ull r; asm("mov.b64 %0, {%1, %1};" : "=l"(r) : "f"(v)); return r;
}
__device__ __forceinline__ void ffma2(ull &d, ull a, ull b){
    asm("fma.rn.f32x2 %0, %1, %2, %0;" : "+l"(d) : "l"(a), "l"(b));
}
__device__ __forceinline__ ull add2(ull a, ull b){
    ull r; asm("add.rn.f32x2 %0, %1, %2;" : "=l"(r) : "l"(a), "l"(b)); return r;
}
__device__ __forceinline__ float2 unpk(ull v){
    float2 f; asm("mov.b64 {%0, %1}, %2;" : "=f"(f.x), "=f"(f.y) : "l"(v)); return f;
}

// ---------------- 1) ConvLSTM (h=c=0 => only 3 input channels, no f gate) -----
__global__ void lstm_kernel(const float* __restrict__ X, const float* __restrict__ w,
                            const float* __restrict__ bias,
                            float* __restrict__ hid, float* __restrict__ cell)
{
    int idx = blockIdx.x*256 + threadIdx.x;
    int x = idx & 127, y = (idx >> 7) & 127, k = (idx >> 14) & 63, b = idx >> 20;
    float ai = bias[k], ao = bias[128+k], ag = bias[192+k];
    const float* Xb = X + b*3*HW;
    const float* wi = w + k*603;
    const float* wo = w + (128+k)*603;
    const float* wg = w + (192+k)*603;
    #pragma unroll
    for (int c = 0; c < 3; c++)
        #pragma unroll
        for (int dy = 0; dy < 3; dy++) {
            int yy = y + dy - 1;
            #pragma unroll
            for (int dx = 0; dx < 3; dx++) {
                int xx = x + dx - 1;
                float v = (yy >= 0 && yy < 128 && xx >= 0 && xx < 128)
                        ? Xb[c*HW + yy*128 + xx] : 0.f;
                int t = c*9 + dy*3 + dx;
                ai = fmaf(wi[t], v, ai);
                ao = fmaf(wo[t], v, ao);
                ag = fmaf(wg[t], v, ag);
            }
        }
    float cc = sigm(ai)*tanhf(ag);
    float hh = sigm(ao)*tanhf(cc);
    hid[idx]  = hh;
    cell[idx] = cc;
}

// ---------------- 2) offset/mask conv, f32x2 packed GEMM ----------------------
__global__ __launch_bounds__(256) void conv_off_kernel(
    const float* __restrict__ xin, const float* __restrict__ lr,
    const float* __restrict__ w0, const float* __restrict__ b0,
    const float* __restrict__ w1, const float* __restrict__ b1,
    float* __restrict__ out0, float* __restrict__ out1)
{
    __shared__ float sTile[16*3*132];    // 16ch x 3 rows x 132 cols (col=gx+1)
    __shared__ float sW[144*32];

    int tid = threadIdx.x;
    int pg = tid & 31;
    int og = tid >> 5;
    int b = blockIdx.y, y = blockIdx.x;
    int y0 = y - 1;

    ull acc[2][4];
    #pragma unroll
    for (int q = 0; q < 2; q++)
        #pragma unroll
        for (int p = 0; p < 4; p++) acc[q][p] = 0ull;

    for (int c0 = 0; c0 < 67; c0 += 16) {
        int cnt = (67 - c0) < 16 ? (67 - c0) : 16;
        for (int i = tid; i < cnt*3; i += 256) {
            int c = i / 3, r = i - c*3;
            float* row = sTile + c*396 + r*132;
            row[0] = 0.f; row[129] = 0.f; row[130] = 0.f; row[131] = 0.f;
        }
        for (int i = tid; i < cnt*96; i += 256) {
            int c = i / 96, rem = i - c*96;
            int r = rem >> 5, q = rem & 31;
            int gy = y0 + r;
            int cg = c0 + c;
            const float* src = (cg < 64) ? (xin + (b*64 + cg)*HW)
                                         : (lr  + (b*3 + (cg-64))*HW);
            float4 v = make_float4(0.f, 0.f, 0.f, 0.f);
            if (gy >= 0 && gy < 128) v = *(const float4*)(src + gy*128 + q*4);
            float* dst = sTile + c*396 + r*132 + 1 + q*4;
            dst[0] = v.x; dst[1] = v.y; dst[2] = v.z; dst[3] = v.w;
        }
        int c09 = c0*9;
        for (int i = tid; i < cnt*288; i += 256) {
            int o = i & 31, tdx = i >> 5;
            float wv = 0.f;
            if (o < 18)      wv = w0[o*603 + c09 + tdx];
            else if (o < 27) wv = w1[(o-18)*603 + c09 + tdx];
            sW[tdx*32 + o] = wv;
        }
        __syncthreads();

        for (int c = 0; c < cnt; c++) {
            #pragma unroll
            for (int ky = 0; ky < 3; ky++) {
                const float* rb = sTile + c*396 + ky*132 + pg*4;
                float4 a4 = *(const float4*)rb;
                float2 a2 = *(const float2*)(rb + 4);
                ull vv[6];
                vv[0] = dup2(a4.x); vv[1] = dup2(a4.y); vv[2] = dup2(a4.z);
                vv[3] = dup2(a4.w); vv[4] = dup2(a2.x); vv[5] = dup2(a2.y);
                #pragma unroll
                for (int kx = 0; kx < 3; kx++) {
                    ulonglong2 w = *(const ulonglong2*)(sW + (c*9 + ky*3 + kx)*32 + og*4);
                    #pragma unroll
                    for (int p = 0; p < 4; p++) {
                        ffma2(acc[0][p], w.x, vv[kx + p]);
                        ffma2(acc[1][p], w.y, vv[kx + p]);
                    }
                }
            }
        }
        __syncthreads();
    }

    int pixb = y*128 + pg*4;
    #pragma unroll
    for (int wp = 0; wp < 2; wp++) {
        int o0 = og*4 + 2*wp;
        float2 a0 = unpk(acc[wp][0]), a1 = unpk(acc[wp][1]);
        float2 a2 = unpk(acc[wp][2]), a3 = unpk(acc[wp][3]);
        if (o0 < 18) {
            float bb = b0[o0];
            *(float4*)(out0 + (b*18 + o0)*HW + pixb) =
                make_float4(a0.x+bb, a1.x+bb, a2.x+bb, a3.x+bb);
        } else if (o0 < 27) {
            float bb = b1[o0-18];
            *(float4*)(out1 + (b*9 + (o0-18))*HW + pixb) =
                make_float4(2.f*sigm(a0.x+bb), 2.f*sigm(a1.x+bb),
                            2.f*sigm(a2.x+bb), 2.f*sigm(a3.x+bb));
        }
        int o1 = o0 + 1;
        if (o1 < 18) {
            float bb = b0[o1];
            *(float4*)(out0 + (b*18 + o1)*HW + pixb) =
                make_float4(a0.y+bb, a1.y+bb, a2.y+bb, a3.y+bb);
        } else if (o1 < 27) {
            float bb = b1[o1-18];
            *(float4*)(out1 + (b*9 + (o1-18))*HW + pixb) =
                make_float4(2.f*sigm(a0.y+bb), 2.f*sigm(a1.y+bb),
                            2.f*sigm(a2.y+bb), 2.f*sigm(a3.y+bb));
        }
    }
}

// ---------------- 2b) small direct conv (final 3-out fuse conv) ---------------
template<int COUT>
__global__ __launch_bounds__(256) void conv_small_kernel(
    const float* __restrict__ xin, const float* __restrict__ lr,
    const float* __restrict__ w0, const float* __restrict__ b0,
    float* __restrict__ out0)
{
    __shared__ float sT[16*10*34];
    __shared__ float sW[COUT*16*9];
    int tid = threadIdx.x;
    int tx = tid & 31, ty = tid >> 5;
    int b = blockIdx.z;
    int x = blockIdx.x*32 + tx, y = blockIdx.y*8 + ty;
    int gx0 = blockIdx.x*32 - 1, gy0 = blockIdx.y*8 - 1;

    float acc[COUT];
    #pragma unroll
    for (int o = 0; o < COUT; o++) acc[o] = 0.f;

    for (int c0 = 0; c0 < 67; c0 += 16) {
        int cnt = (67 - c0) < 16 ? (67 - c0) : 16;
        for (int i = tid; i < cnt*340; i += 256) {
            int c = i / 340, rem = i - c*340;
            int r = rem / 34, col = rem - r*34;
            int gy = gy0 + r, gx = gx0 + col;
            int cg = c0 + c;
            const float* src = (cg < 64) ? (xin + (b*64 + cg)*HW)
                                         : (lr  + (b*3 + (cg-64))*HW);
            sT[i] = (gy >= 0 && gy < 128 && gx >= 0 && gx < 128)
                  ? src[gy*128 + gx] : 0.f;
        }
        int wtot = COUT*cnt*9;
        for (int i = tid; i < wtot; i += 256) {
            int o = i / (cnt*9), rem = i - o*(cnt*9);
            sW[o*144 + rem] = w0[o*603 + c0*9 + rem];
        }
        __syncthreads();
        for (int c = 0; c < cnt; c++) {
            float win[9];
            #pragma unroll
            for (int r = 0; r < 3; r++)
                #pragma unroll
                for (int q = 0; q < 3; q++)
                    win[r*3+q] = sT[c*340 + (ty+r)*34 + (tx+q)];
            #pragma unroll
            for (int o = 0; o < COUT; o++) {
                #pragma unroll
                for (int t = 0; t < 9; t++)
                    acc[o] = fmaf(sW[o*144 + c*9 + t], win[t], acc[o]);
            }
        }
        __syncthreads();
    }
    int pix = y*128 + x;
    #pragma unroll
    for (int o = 0; o < COUT; o++)
        out0[(b*COUT + o)*HW + pix] = acc[o] + b0[o];
}

// ---------------- 3) deform: gather + 64x603 GEMM, f32x2, K-chunked -----------
#define DF_SIDX  4608
#define DF_SV    (4608 + 1152)
#define DF_SWC   (DF_SV + 67*132)
#define DF_SMEM_BYTES ((DF_SWC + 67*64) * 4)

__global__ __launch_bounds__(256, 3) void deform_kernel(
    const float* __restrict__ xin, const float* __restrict__ lr,
    const float* __restrict__ wmain, const float* __restrict__ bias,
    float* __restrict__ out)
{
    extern __shared__ float smem[];
    float4* sWt = (float4*)smem;
    int*    sIdx= (int*)(smem + DF_SIDX);
    float*  sV  = smem + DF_SV;
    float*  sWc = smem + DF_SWC;

    int tid = threadIdx.x;
    int b = blockIdx.y, y = blockIdx.x;

    for (int e = tid; e < 1152; e += 256) {
        int p = e & 127, k = e >> 7;
        int pix = y*128 + p;
        float offy = g_off [(b*18 + 2*k    )*HW + pix];
        float offx = g_off [(b*18 + 2*k + 1)*HW + pix];
        float m    = g_mask[(b*9  + k      )*HW + pix];
        int ky = k / 3, kx = k - ky*3;
        float py = (float)(y + ky - 1) + offy;
        float px = (float)(p + kx - 1) + offx;
        float fy = floorf(py), fx = floorf(px);
        float wy = py - fy,    wx = px - fx;
        int iy = (int)fy, ix = (int)fx;
        bool vy0 = (iy   >= 0 && iy   <= 127);
        bool vy1 = (iy+1 >= 0 && iy+1 <= 127);
        bool vx0 = (ix   >= 0 && ix   <= 127);
        bool vx1 = (ix+1 >= 0 && ix+1 <= 127);
        float4 wv;
        wv.x = (1.f-wy)*(1.f-wx)*m * ((vy0 && vx0) ? 1.f : 0.f);
        wv.y = (1.f-wy)*wx      *m * ((vy0 && vx1) ? 1.f : 0.f);
        wv.z = wy*(1.f-wx)      *m * ((vy1 && vx0) ? 1.f : 0.f);
        wv.w = wy*wx            *m * ((vy1 && vx1) ? 1.f : 0.f);
        sWt[e] = wv;
        int iy0 = min(max(iy,   0), 127), iy1 = min(max(iy+1, 0), 127);
        int ix0 = min(max(ix,   0), 127), ix1 = min(max(ix+1, 0), 127);
        sIdx[e] = iy0 | (iy1 << 8) | (ix0 << 16) | (ix1 << 24);
    }
    __syncthreads();

    const float* xb = xin + b*64*HW;
    const float* lb = lr  + b*3*HW;
    int pg = tid & 31, og = tid >> 5;

    ull acc[4][4];
    #pragma unroll
    for (int q = 0; q < 4; q++)
        #pragma unroll
        for (int p = 0; p < 4; p++) acc[q][p] = 0ull;

    for (int c0 = 0; c0 < 603; c0 += 67) {
        for (int i = tid; i < 67*64; i += 256) {
            int o = i & 63, j = i >> 6;
            sWc[j*64 + o] = wmain[o*603 + c0 + j];
        }
        #pragma unroll 2
        for (int e = tid; e < 67*128; e += 256) {
            int p = e & 127, j = e >> 7;
            int kk = c0 + j;
            int c = kk / 9, k = kk - c*9;
            int mi = (k << 7) | p;
            float4 wt = sWt[mi];
            int pk = sIdx[mi];
            int iy0 =  pk        & 255, iy1 = (pk >> 8)  & 255;
            int ix0 = (pk >> 16) & 255, ix1 = (pk >> 24) & 255;
            const float* src = (c < 64) ? (xb + c*HW) : (lb + (c-64)*HW);
            float v = wt.x * __ldg(src + iy0*128 + ix0)
                    + wt.y * __ldg(src + iy0*128 + ix1)
                    + wt.z * __ldg(src + iy1*128 + ix0)
                    + wt.w * __ldg(src + iy1*128 + ix1);
            sV[j*132 + p] = v;
        }
        __syncthreads();

        const float* vp = sV + pg*4;
        const float* wp_ = sWc + og*8;
        #pragma unroll 4
        for (int j = 0; j < 67; j++) {
            ulonglong2 wA = *(const ulonglong2*)(wp_ + j*64);
            ulonglong2 wB = *(const ulonglong2*)(wp_ + j*64 + 4);
            float4 v = *(const float4*)(vp + j*132);
            ull v0 = dup2(v.x), v1 = dup2(v.y), v2 = dup2(v.z), v3 = dup2(v.w);
            ffma2(acc[0][0], wA.x, v0); ffma2(acc[0][1], wA.x, v1);
            ffma2(acc[0][2], wA.x, v2); ffma2(acc[0][3], wA.x, v3);
            ffma2(acc[1][0], wA.y, v0); ffma2(acc[1][1], wA.y, v1);
            ffma2(acc[1][2], wA.y, v2); ffma2(acc[1][3], wA.y, v3);
            ffma2(acc[2][0], wB.x, v0); ffma2(acc[2][1], wB.x, v1);
            ffma2(acc[2][2], wB.x, v2); ffma2(acc[2][3], wB.x, v3);
            ffma2(acc[3][0], wB.y, v0); ffma2(acc[3][1], wB.y, v1);
            ffma2(acc[3][2], wB.y, v2); ffma2(acc[3][3], wB.y, v3);
        }
        __syncthreads();
    }

    int pixb = y*128 + pg*4;
    #pragma unroll
    for (int wp = 0; wp < 4; wp++) {
        int o0 = og*8 + 2*wp;
        float2 a0 = unpk(acc[wp][0]), a1 = unpk(acc[wp][1]);
        float2 a2 = unpk(acc[wp][2]), a3 = unpk(acc[wp][3]);
        float bb0 = bias[o0], bb1 = bias[o0+1];
        *(float4*)(out + (b*64 + o0)*HW + pixb) =
            make_float4(a0.x+bb0, a1.x+bb0, a2.x+bb0, a3.x+bb0);
        *(float4*)(out + (b*64 + o0+1)*HW + pixb) =
            make_float4(a0.y+bb1, a1.y+bb1, a2.y+bb1, a3.y+bb1);
    }
}

// ---------------- 4) global average pool --------------------------------------
__global__ void pool_kernel(const float* __restrict__ xf)
{
    __shared__ float red[256];
    int bc = blockIdx.x, tid = threadIdx.x;
    float s = 0.f;
    const float* p = xf + bc*HW;
    for (int i = tid; i < HW; i += 256) s += p[i];
    red[tid] = s; __syncthreads();
    for (int st = 128; st > 0; st >>= 1) {
        if (tid < st) red[tid] += red[tid + st];
        __syncthreads();
    }
    if (tid == 0) g_pool[bc] = red[0] * (1.f/HW);
}

// ---------------- 5) channel-filter MLP ---------------------------------------
__global__ void ch_kernel(const float* __restrict__ ch_w1, const float* __restrict__ ch_b1,
                          const float* __restrict__ ch_w2, const float* __restrict__ ch_b2)
{
    int t = threadIdx.x;
    if (t >= 64) return;
    int b = t >> 4, s = t & 15;
    float h1[4];
    #pragma unroll
    for (int m = 0; m < 4; m++) {
        float a = ch_b1[s*4 + m];
        #pragma unroll
        for (int c = 0; c < 3; c++) a = fmaf(g_pool[b*3 + c], ch_w1[(s*4 + m)*3 + c], a);
        h1[m] = fmaxf(a, 0.f);
    }
    for (int k = 0; k < 27; k++) {
        float a = ch_b2[s*27 + k];
        #pragma unroll
        for (int m = 0; m < 4; m++) a = fmaf(h1[m], ch_w2[(s*27 + k)*4 + m], a);
        g_ch[(b*16 + s)*27 + k] = a;
    }
}

// ---------------- 6) DDF up: f32x2 s-pair packed, 2 threads/px ----------------
// Grid (128, B_), 256 threads: one 128-px row per CTA.
// Thread: px = tid&127, half = tid>>7 handles s-pairs i in [half*4, half*4+4).
__global__ __launch_bounds__(256) void ddf_kernel(
    const float* __restrict__ spw, const float* __restrict__ spb,
    float* __restrict__ out)
{
    __shared__ __align__(16) float2 sSpw2[8*9*28];   // [i][k][j] pairs (s=2i, 2i+1)
    __shared__ float2 sSpb2[72];                      // [i][k]
    __shared__ float2 sCh2[216];                      // [i][j=c*9+k]
    __shared__ float sX[3*3*132];                     // 3ch x 3rows x 132 cols

    int tid = threadIdx.x;
    int b = blockIdx.y, y = blockIdx.x;

    // stage interleaved spatial weights (pad j=27 with 0)
    for (int idx = tid; idx < 2016; idx += 256) {
        int i = idx / 252, rem = idx - i*252;
        int k = rem / 28, j = rem - k*28;
        float v0 = 0.f, v1 = 0.f;
        if (j < 27) {
            v0 = spw[((2*i  )*9 + k)*27 + j];
            v1 = spw[((2*i+1)*9 + k)*27 + j];
        }
        sSpw2[idx] = make_float2(v0, v1);
    }
    if (tid < 72) {
        int i = tid / 9, k = tid - i*9;
        sSpb2[tid] = make_float2(spb[(2*i)*9 + k], spb[(2*i+1)*9 + k]);
    }
    if (tid < 216) {
        int i = tid / 27, j = tid - i*27;
        sCh2[tid] = make_float2(g_ch[b*432 + (2*i)*27 + j],
                                g_ch[b*432 + (2*i+1)*27 + j]);
    }
    // stage input window rows (3 ch x rows y-1..y+1, col = gx+1 in [0,131])
    if (tid < 9) {
        float* row = sX + tid*132;
        row[0] = 0.f; row[129] = 0.f; row[130] = 0.f; row[131] = 0.f;
    }
    for (int idx = tid; idx < 288; idx += 256) {
        int row9 = idx >> 5, q = idx & 31;
        int c = row9 / 3, r = row9 - c*3;
        int gy = y - 1 + r;
        float4 v = make_float4(0.f, 0.f, 0.f, 0.f);
        if (gy >= 0 && gy < 128)
            v = *(const float4*)(g_xfin + (b*3 + c)*HW + gy*128 + q*4);
        float* dst = sX + row9*132 + 1 + q*4;
        dst[0] = v.x; dst[1] = v.y; dst[2] = v.z; dst[3] = v.w;
    }
    __syncthreads();

    int px = tid & 127, half = tid >> 7;

    // build dup2'd window (28 entries, last = 0 for the padded j)
    ull winD[28];
    #pragma unroll
    for (int c = 0; c < 3; c++)
        #pragma unroll
        for (int r = 0; r < 3; r++)
            #pragma unroll
            for (int q = 0; q < 3; q++)
                winD[c*9 + r*3 + q] = dup2(sX[(c*3 + r)*132 + px + q]);
    winD[27] = 0ull;

    float* ob = out + b*3*(512*512);
    int i0 = half*4;
    #pragma unroll 1
    for (int i = i0; i < i0 + 4; i++) {
        ull a0 = 0ull, a1 = 0ull, a2 = 0ull;
        #pragma unroll
        for (int k = 0; k < 9; k++) {
            ull spv = *(const ull*)&sSpb2[i*9 + k];
            const ulonglong2* w2 = (const ulonglong2*)(sSpw2 + (i*9 + k)*28);
            #pragma unroll
            for (int j2 = 0; j2 < 14; j2++) {
                ulonglong2 w = w2[j2];
                ffma2(spv, w.x, winD[j2*2]);
                ffma2(spv, w.y, winD[j2*2 + 1]);
            }
            ull t0 = add2(*(const ull*)&sCh2[i*27 + k],      spv);
            ull t1 = add2(*(const ull*)&sCh2[i*27 + 9 + k],  spv);
            ull t2 = add2(*(const ull*)&sCh2[i*27 + 18 + k], spv);
            ffma2(a0, winD[k],      t0);
            ffma2(a1, winD[9 + k],  t1);
            ffma2(a2, winD[18 + k], t2);
        }
        float2 r0 = unpk(a0), r1 = unpk(a1), r2 = unpk(a2);
        int s0 = 2*i, s1 = 2*i + 1;
        int oy0 = (y << 2) + (s0 >> 2), ox0 = (px << 2) + (s0 & 3);
        int oy1 = (y << 2) + (s1 >> 2), ox1 = (px << 2) + (s1 & 3);
        ob[0*262144 + oy0*512 + ox0] = fminf(fmaxf(r0.x, 0.f), 255.f);
        ob[1*262144 + oy0*512 + ox0] = fminf(fmaxf(r1.x, 0.f), 255.f);
        ob[2*262144 + oy0*512 + ox0] = fminf(fmaxf(r2.x, 0.f), 255.f);
        ob[0*262144 + oy1*512 + ox1] = fminf(fmaxf(r0.y, 0.f), 255.f);
        ob[1*262144 + oy1*512 + ox1] = fminf(fmaxf(r1.y, 0.f), 255.f);
        ob[2*262144 + oy1*512 + ox1] = fminf(fmaxf(r2.y, 0.f), 255.f);
    }
}

// ---------------- host orchestration ------------------------------------------
extern "C" void kernel_launch(void* const* d_in, const int* in_sizes, int n_in,
                              void* d_out, int out_size)
{
    const float* X      = (const float*)d_in[0];
    const float* lstm_w = (const float*)d_in[1];
    const float* lstm_b = (const float*)d_in[2];
    const float* dw[3][6];
    for (int i = 0; i < 3; i++)
        for (int j = 0; j < 6; j++)
            dw[i][j] = (const float*)d_in[3 + i*6 + j];   // ow, ob, mw, mb, w, b
    const float* conv_w = (const float*)d_in[21];
    const float* conv_b = (const float*)d_in[22];
    const float* sp_w   = (const float*)d_in[23];
    const float* sp_b   = (const float*)d_in[24];
    const float* ch_w1  = (const float*)d_in[25];
    const float* ch_b1  = (const float*)d_in[26];
    const float* ch_w2  = (const float*)d_in[27];
    const float* ch_b2  = (const float*)d_in[28];

    float* out_main = (float*)d_out;                     // [4,3,512,512]
    float* hid      = out_main + 4*3*512*512;            // [4,64,128,128]
    float* cell     = hid + 4*64*128*128;                // [4,64,128,128]

    void *pxb0, *pxb1, *poff, *pmask, *pxfin;
    cudaGetSymbolAddress(&pxb0, g_xbuf0);
    cudaGetSymbolAddress(&pxb1, g_xbuf1);
    cudaGetSymbolAddress(&poff,  g_off);
    cudaGetSymbolAddress(&pmask, g_mask);
    cudaGetSymbolAddress(&pxfin, g_xfin);
    float* xb0 = (float*)pxb0;
    float* xb1 = (float*)pxb1;
    float* off_p  = (float*)poff;
    float* mask_p = (float*)pmask;
    float* xfin_p = (float*)pxfin;

    cudaFuncSetAttribute(deform_kernel, cudaFuncAttributeMaxDynamicSharedMemorySize,
                         DF_SMEM_BYTES);

    dim3 rowGrid(128, B_);
    dim3 convGrid(4, 16, B_);

    lstm_kernel<<<16384, 256>>>(X, lstm_w, lstm_b, hid, cell);

    conv_off_kernel<<<rowGrid, 256>>>(hid, X, dw[0][0], dw[0][1],
                                      dw[0][2], dw[0][3], off_p, mask_p);
    deform_kernel<<<rowGrid, 256, DF_SMEM_BYTES>>>(hid, X, dw[0][4], dw[0][5], xb0);

    conv_off_kernel<<<rowGrid, 256>>>(xb0, X, dw[1][0], dw[1][1],
                                      dw[1][2], dw[1][3], off_p, mask_p);
    deform_kernel<<<rowGrid, 256, DF_SMEM_BYTES>>>(xb0, X, dw[1][4], dw[1][5], xb1);

    conv_off_kernel<<<rowGrid, 256>>>(xb1, X, dw[2][0], dw[2][1],
                                      dw[2][2], dw[2][3], off_p, mask_p);
    deform_kernel<<<rowGrid, 256, DF_SMEM_BYTES>>>(xb1, X, dw[2][4], dw[2][5], xb0);

    conv_small_kernel<3><<<convGrid, 256>>>(xb0, X, conv_w, conv_b, xfin_p);

    pool_kernel<<<B_*3, 256>>>(xfin_p);
    ch_kernel<<<1, 64>>>(ch_w1, ch_b1, ch_w2, ch_b2);
    ddf_kernel<<<rowGrid, 256>>>(sp_w, sp_b, out_main);
}

// round 10
// speedup vs baseline: 1.8473x; 1.0175x over previous
#include <cuda_runtime.h>
#include <math.h>

#define HW   16384
#define B_   4

// ---------------- scratch ------------------------------------------------------
__device__ float g_xbuf0[B_*64*HW];
__device__ float g_xbuf1[B_*64*HW];
__device__ float g_off  [B_*18*HW];
__device__ float g_mask [B_*9*HW];
__device__ float g_xfin [B_*3*HW];
__device__ float g_ch   [B_*16*27];
__device__ float g_pool [B_*3];

__device__ __forceinline__ float sigm(float v){ return 1.f/(1.f+__expf(-v)); }

// ---- packed fp32x2 helpers ----------------------------------------------------
typedef unsigned long long ull;
__device__ __forceinline__ ull dup2(float v){
    ull r; asm("mov.b64 %0, {%1, %1};" : "=l"(r) : "f"(v)); return r;
}
__device__ __forceinline__ void ffma2(ull &d, ull a, ull b){
    asm("fma.rn.f32x2 %0, %1, %2, %0;" : "+l"(d) : "l"(a), "l"(b));
}
__device__ __forceinline__ ull add2(ull a, ull b){
    ull r; asm("add.rn.f32x2 %0, %1, %2;" : "=l"(r) : "l"(a), "l"(b)); return r;
}
__device__ __forceinline__ float2 unpk(ull v){
    float2 f; asm("mov.b64 {%0, %1}, %2;" : "=f"(f.x), "=f"(f.y) : "l"(v)); return f;
}

// ---------------- 0) launch-index shift (so ncu -s 5 captures deform) ---------
__global__ void shift_kernel() {}

// ---------------- 1) ConvLSTM: row-CTA, smem-staged, f32x2 k-pairs ------------
// h=c=0 at t=0 => only 3 input channels contribute, f gate vanishes.
__global__ __launch_bounds__(256) void lstm_kernel(
    const float* __restrict__ X, const float* __restrict__ w,
    const float* __restrict__ bias,
    float* __restrict__ hid, float* __restrict__ cell)
{
    __shared__ float sX[9*132];            // 3ch x 3rows x 132 (col = gx+1)
    __shared__ float2 sW2[32*3*28];        // [kpair][gate i/o/g][tap0..27]
    __shared__ float2 sB2[32*3];           // [kpair][gate]

    int tid = threadIdx.x;
    int b = blockIdx.y, y = blockIdx.x;

    // stage weight pairs (k, k+1); tap 27 padded 0
    for (int i = tid; i < 2688; i += 256) {
        int kp = i / 84, rem = i - kp*84;
        int g = rem / 28, t = rem - g*28;
        int gbase = (g == 0) ? 0 : (g == 1) ? 128 : 192;
        float v0 = 0.f, v1 = 0.f;
        if (t < 27) {
            v0 = w[(gbase + 2*kp    )*603 + t];
            v1 = w[(gbase + 2*kp + 1)*603 + t];
        }
        sW2[i] = make_float2(v0, v1);
    }
    if (tid < 96) {
        int kp = tid / 3, g = tid - kp*3;
        int gbase = (g == 0) ? 0 : (g == 1) ? 128 : 192;
        sB2[tid] = make_float2(bias[gbase + 2*kp], bias[gbase + 2*kp + 1]);
    }
    // stage X window rows
    if (tid < 9) {
        float* row = sX + tid*132;
        row[0] = 0.f; row[129] = 0.f; row[130] = 0.f; row[131] = 0.f;
    }
    for (int idx = tid; idx < 288; idx += 256) {
        int row9 = idx >> 5, q = idx & 31;
        int c = row9 / 3, r = row9 - c*3;
        int gy = y - 1 + r;
        float4 v = make_float4(0.f, 0.f, 0.f, 0.f);
        if (gy >= 0 && gy < 128)
            v = *(const float4*)(X + (b*3 + c)*HW + gy*128 + q*4);
        float* dst = sX + row9*132 + 1 + q*4;
        dst[0] = v.x; dst[1] = v.y; dst[2] = v.z; dst[3] = v.w;
    }
    __syncthreads();

    int px = tid & 127, kh = tid >> 7;

    ull win[28];
    #pragma unroll
    for (int c = 0; c < 3; c++)
        #pragma unroll
        for (int r = 0; r < 3; r++)
            #pragma unroll
            for (int q = 0; q < 3; q++)
                win[c*9 + r*3 + q] = dup2(sX[(c*3 + r)*132 + px + q]);
    win[27] = 0ull;

    int pix = y*128 + px;
    int kp0 = kh*16;
    #pragma unroll 1
    for (int kp = kp0; kp < kp0 + 16; kp++) {
        ull aI = *(const ull*)&sB2[kp*3 + 0];
        ull aO = *(const ull*)&sB2[kp*3 + 1];
        ull aG = *(const ull*)&sB2[kp*3 + 2];
        const ulonglong2* wI = (const ulonglong2*)(sW2 + (kp*3 + 0)*28);
        const ulonglong2* wO = (const ulonglong2*)(sW2 + (kp*3 + 1)*28);
        const ulonglong2* wG = (const ulonglong2*)(sW2 + (kp*3 + 2)*28);
        #pragma unroll
        for (int t2 = 0; t2 < 14; t2++) {
            ulonglong2 wi = wI[t2];
            ffma2(aI, wi.x, win[2*t2]); ffma2(aI, wi.y, win[2*t2 + 1]);
            ulonglong2 wo = wO[t2];
            ffma2(aO, wo.x, win[2*t2]); ffma2(aO, wo.y, win[2*t2 + 1]);
            ulonglong2 wg = wG[t2];
            ffma2(aG, wg.x, win[2*t2]); ffma2(aG, wg.y, win[2*t2 + 1]);
        }
        float2 ai = unpk(aI), ao = unpk(aO), ag = unpk(aG);
        float c0 = sigm(ai.x)*tanhf(ag.x);
        float c1 = sigm(ai.y)*tanhf(ag.y);
        float h0 = sigm(ao.x)*tanhf(c0);
        float h1 = sigm(ao.y)*tanhf(c1);
        int k0 = 2*kp;
        hid [(b*64 + k0    )*HW + pix] = h0;
        hid [(b*64 + k0 + 1)*HW + pix] = h1;
        cell[(b*64 + k0    )*HW + pix] = c0;
        cell[(b*64 + k0 + 1)*HW + pix] = c1;
    }
}

// ---------------- 2) offset/mask conv, f32x2 packed GEMM ----------------------
__global__ __launch_bounds__(256) void conv_off_kernel(
    const float* __restrict__ xin, const float* __restrict__ lr,
    const float* __restrict__ w0, const float* __restrict__ b0,
    const float* __restrict__ w1, const float* __restrict__ b1,
    float* __restrict__ out0, float* __restrict__ out1)
{
    __shared__ float sTile[16*3*132];    // 16ch x 3 rows x 132 cols (col=gx+1)
    __shared__ float sW[144*32];

    int tid = threadIdx.x;
    int pg = tid & 31;
    int og = tid >> 5;
    int b = blockIdx.y, y = blockIdx.x;
    int y0 = y - 1;

    ull acc[2][4];
    #pragma unroll
    for (int q = 0; q < 2; q++)
        #pragma unroll
        for (int p = 0; p < 4; p++) acc[q][p] = 0ull;

    for (int c0 = 0; c0 < 67; c0 += 16) {
        int cnt = (67 - c0) < 16 ? (67 - c0) : 16;
        for (int i = tid; i < cnt*3; i += 256) {
            int c = i / 3, r = i - c*3;
            float* row = sTile + c*396 + r*132;
            row[0] = 0.f; row[129] = 0.f; row[130] = 0.f; row[131] = 0.f;
        }
        for (int i = tid; i < cnt*96; i += 256) {
            int c = i / 96, rem = i - c*96;
            int r = rem >> 5, q = rem & 31;
            int gy = y0 + r;
            int cg = c0 + c;
            const float* src = (cg < 64) ? (xin + (b*64 + cg)*HW)
                                         : (lr  + (b*3 + (cg-64))*HW);
            float4 v = make_float4(0.f, 0.f, 0.f, 0.f);
            if (gy >= 0 && gy < 128) v = *(const float4*)(src + gy*128 + q*4);
            float* dst = sTile + c*396 + r*132 + 1 + q*4;
            dst[0] = v.x; dst[1] = v.y; dst[2] = v.z; dst[3] = v.w;
        }
        int c09 = c0*9;
        for (int i = tid; i < cnt*288; i += 256) {
            int o = i & 31, tdx = i >> 5;
            float wv = 0.f;
            if (o < 18)      wv = w0[o*603 + c09 + tdx];
            else if (o < 27) wv = w1[(o-18)*603 + c09 + tdx];
            sW[tdx*32 + o] = wv;
        }
        __syncthreads();

        for (int c = 0; c < cnt; c++) {
            #pragma unroll
            for (int ky = 0; ky < 3; ky++) {
                const float* rb = sTile + c*396 + ky*132 + pg*4;
                float4 a4 = *(const float4*)rb;
                float2 a2 = *(const float2*)(rb + 4);
                ull vv[6];
                vv[0] = dup2(a4.x); vv[1] = dup2(a4.y); vv[2] = dup2(a4.z);
                vv[3] = dup2(a4.w); vv[4] = dup2(a2.x); vv[5] = dup2(a2.y);
                #pragma unroll
                for (int kx = 0; kx < 3; kx++) {
                    ulonglong2 w = *(const ulonglong2*)(sW + (c*9 + ky*3 + kx)*32 + og*4);
                    #pragma unroll
                    for (int p = 0; p < 4; p++) {
                        ffma2(acc[0][p], w.x, vv[kx + p]);
                        ffma2(acc[1][p], w.y, vv[kx + p]);
                    }
                }
            }
        }
        __syncthreads();
    }

    int pixb = y*128 + pg*4;
    #pragma unroll
    for (int wp = 0; wp < 2; wp++) {
        int o0 = og*4 + 2*wp;
        float2 a0 = unpk(acc[wp][0]), a1 = unpk(acc[wp][1]);
        float2 a2 = unpk(acc[wp][2]), a3 = unpk(acc[wp][3]);
        if (o0 < 18) {
            float bb = b0[o0];
            *(float4*)(out0 + (b*18 + o0)*HW + pixb) =
                make_float4(a0.x+bb, a1.x+bb, a2.x+bb, a3.x+bb);
        } else if (o0 < 27) {
            float bb = b1[o0-18];
            *(float4*)(out1 + (b*9 + (o0-18))*HW + pixb) =
                make_float4(2.f*sigm(a0.x+bb), 2.f*sigm(a1.x+bb),
                            2.f*sigm(a2.x+bb), 2.f*sigm(a3.x+bb));
        }
        int o1 = o0 + 1;
        if (o1 < 18) {
            float bb = b0[o1];
            *(float4*)(out0 + (b*18 + o1)*HW + pixb) =
                make_float4(a0.y+bb, a1.y+bb, a2.y+bb, a3.y+bb);
        } else if (o1 < 27) {
            float bb = b1[o1-18];
            *(float4*)(out1 + (b*9 + (o1-18))*HW + pixb) =
                make_float4(2.f*sigm(a0.y+bb), 2.f*sigm(a1.y+bb),
                            2.f*sigm(a2.y+bb), 2.f*sigm(a3.y+bb));
        }
    }
}

// ---------------- 2b) small direct conv (final 3-out fuse conv) ---------------
template<int COUT>
__global__ __launch_bounds__(256) void conv_small_kernel(
    const float* __restrict__ xin, const float* __restrict__ lr,
    const float* __restrict__ w0, const float* __restrict__ b0,
    float* __restrict__ out0)
{
    __shared__ float sT[16*10*34];
    __shared__ float sW[COUT*16*9];
    int tid = threadIdx.x;
    int tx = tid & 31, ty = tid >> 5;
    int b = blockIdx.z;
    int x = blockIdx.x*32 + tx, y = blockIdx.y*8 + ty;
    int gx0 = blockIdx.x*32 - 1, gy0 = blockIdx.y*8 - 1;

    float acc[COUT];
    #pragma unroll
    for (int o = 0; o < COUT; o++) acc[o] = 0.f;

    for (int c0 = 0; c0 < 67; c0 += 16) {
        int cnt = (67 - c0) < 16 ? (67 - c0) : 16;
        for (int i = tid; i < cnt*340; i += 256) {
            int c = i / 340, rem = i - c*340;
            int r = rem / 34, col = rem - r*34;
            int gy = gy0 + r, gx = gx0 + col;
            int cg = c0 + c;
            const float* src = (cg < 64) ? (xin + (b*64 + cg)*HW)
                                         : (lr  + (b*3 + (cg-64))*HW);
            sT[i] = (gy >= 0 && gy < 128 && gx >= 0 && gx < 128)
                  ? src[gy*128 + gx] : 0.f;
        }
        int wtot = COUT*cnt*9;
        for (int i = tid; i < wtot; i += 256) {
            int o = i / (cnt*9), rem = i - o*(cnt*9);
            sW[o*144 + rem] = w0[o*603 + c0*9 + rem];
        }
        __syncthreads();
        for (int c = 0; c < cnt; c++) {
            float win[9];
            #pragma unroll
            for (int r = 0; r < 3; r++)
                #pragma unroll
                for (int q = 0; q < 3; q++)
                    win[r*3+q] = sT[c*340 + (ty+r)*34 + (tx+q)];
            #pragma unroll
            for (int o = 0; o < COUT; o++) {
                #pragma unroll
                for (int t = 0; t < 9; t++)
                    acc[o] = fmaf(sW[o*144 + c*9 + t], win[t], acc[o]);
            }
        }
        __syncthreads();
    }
    int pix = y*128 + x;
    #pragma unroll
    for (int o = 0; o < COUT; o++)
        out0[(b*COUT + o)*HW + pix] = acc[o] + b0[o];
}

// ---------------- 3) deform: gather + 64x603 GEMM, f32x2, K-chunked -----------
#define DF_SIDX  4608
#define DF_SV    (4608 + 1152)
#define DF_SWC   (DF_SV + 67*132)
#define DF_SMEM_BYTES ((DF_SWC + 67*64) * 4)

__global__ __launch_bounds__(256, 3) void deform_kernel(
    const float* __restrict__ xin, const float* __restrict__ lr,
    const float* __restrict__ wmain, const float* __restrict__ bias,
    float* __restrict__ out)
{
    extern __shared__ float smem[];
    float4* sWt = (float4*)smem;
    int*    sIdx= (int*)(smem + DF_SIDX);
    float*  sV  = smem + DF_SV;
    float*  sWc = smem + DF_SWC;

    int tid = threadIdx.x;
    int b = blockIdx.y, y = blockIdx.x;

    for (int e = tid; e < 1152; e += 256) {
        int p = e & 127, k = e >> 7;
        int pix = y*128 + p;
        float offy = g_off [(b*18 + 2*k    )*HW + pix];
        float offx = g_off [(b*18 + 2*k + 1)*HW + pix];
        float m    = g_mask[(b*9  + k      )*HW + pix];
        int ky = k / 3, kx = k - ky*3;
        float py = (float)(y + ky - 1) + offy;
        float px = (float)(p + kx - 1) + offx;
        float fy = floorf(py), fx = floorf(px);
        float wy = py - fy,    wx = px - fx;
        int iy = (int)fy, ix = (int)fx;
        bool vy0 = (iy   >= 0 && iy   <= 127);
        bool vy1 = (iy+1 >= 0 && iy+1 <= 127);
        bool vx0 = (ix   >= 0 && ix   <= 127);
        bool vx1 = (ix+1 >= 0 && ix+1 <= 127);
        float4 wv;
        wv.x = (1.f-wy)*(1.f-wx)*m * ((vy0 && vx0) ? 1.f : 0.f);
        wv.y = (1.f-wy)*wx      *m * ((vy0 && vx1) ? 1.f : 0.f);
        wv.z = wy*(1.f-wx)      *m * ((vy1 && vx0) ? 1.f : 0.f);
        wv.w = wy*wx            *m * ((vy1 && vx1) ? 1.f : 0.f);
        sWt[e] = wv;
        int iy0 = min(max(iy,   0), 127), iy1 = min(max(iy+1, 0), 127);
        int ix0 = min(max(ix,   0), 127), ix1 = min(max(ix+1, 0), 127);
        sIdx[e] = iy0 | (iy1 << 8) | (ix0 << 16) | (ix1 << 24);
    }
    __syncthreads();

    const float* xb = xin + b*64*HW;
    const float* lb = lr  + b*3*HW;
    int pg = tid & 31, og = tid >> 5;

    ull acc[4][4];
    #pragma unroll
    for (int q = 0; q < 4; q++)
        #pragma unroll
        for (int p = 0; p < 4; p++) acc[q][p] = 0ull;

    for (int c0 = 0; c0 < 603; c0 += 67) {
        for (int i = tid; i < 67*64; i += 256) {
            int o = i & 63, j = i >> 6;
            sWc[j*64 + o] = wmain[o*603 + c0 + j];
        }
        #pragma unroll 2
        for (int e = tid; e < 67*128; e += 256) {
            int p = e & 127, j = e >> 7;
            int kk = c0 + j;
            int c = kk / 9, k = kk - c*9;
            int mi = (k << 7) | p;
            float4 wt = sWt[mi];
            int pk = sIdx[mi];
            int iy0 =  pk        & 255, iy1 = (pk >> 8)  & 255;
            int ix0 = (pk >> 16) & 255, ix1 = (pk >> 24) & 255;
            const float* src = (c < 64) ? (xb + c*HW) : (lb + (c-64)*HW);
            float v = wt.x * __ldg(src + iy0*128 + ix0)
                    + wt.y * __ldg(src + iy0*128 + ix1)
                    + wt.z * __ldg(src + iy1*128 + ix0)
                    + wt.w * __ldg(src + iy1*128 + ix1);
            sV[j*132 + p] = v;
        }
        __syncthreads();

        const float* vp = sV + pg*4;
        const float* wp_ = sWc + og*8;
        #pragma unroll 4
        for (int j = 0; j < 67; j++) {
            ulonglong2 wA = *(const ulonglong2*)(wp_ + j*64);
            ulonglong2 wB = *(const ulonglong2*)(wp_ + j*64 + 4);
            float4 v = *(const float4*)(vp + j*132);
            ull v0 = dup2(v.x), v1 = dup2(v.y), v2 = dup2(v.z), v3 = dup2(v.w);
            ffma2(acc[0][0], wA.x, v0); ffma2(acc[0][1], wA.x, v1);
            ffma2(acc[0][2], wA.x, v2); ffma2(acc[0][3], wA.x, v3);
            ffma2(acc[1][0], wA.y, v0); ffma2(acc[1][1], wA.y, v1);
            ffma2(acc[1][2], wA.y, v2); ffma2(acc[1][3], wA.y, v3);
            ffma2(acc[2][0], wB.x, v0); ffma2(acc[2][1], wB.x, v1);
            ffma2(acc[2][2], wB.x, v2); ffma2(acc[2][3], wB.x, v3);
            ffma2(acc[3][0], wB.y, v0); ffma2(acc[3][1], wB.y, v1);
            ffma2(acc[3][2], wB.y, v2); ffma2(acc[3][3], wB.y, v3);
        }
        __syncthreads();
    }

    int pixb = y*128 + pg*4;
    #pragma unroll
    for (int wp = 0; wp < 4; wp++) {
        int o0 = og*8 + 2*wp;
        float2 a0 = unpk(acc[wp][0]), a1 = unpk(acc[wp][1]);
        float2 a2 = unpk(acc[wp][2]), a3 = unpk(acc[wp][3]);
        float bb0 = bias[o0], bb1 = bias[o0+1];
        *(float4*)(out + (b*64 + o0)*HW + pixb) =
            make_float4(a0.x+bb0, a1.x+bb0, a2.x+bb0, a3.x+bb0);
        *(float4*)(out + (b*64 + o0+1)*HW + pixb) =
            make_float4(a0.y+bb1, a1.y+bb1, a2.y+bb1, a3.y+bb1);
    }
}

// ---------------- 4) global average pool --------------------------------------
__global__ void pool_kernel(const float* __restrict__ xf)
{
    __shared__ float red[256];
    int bc = blockIdx.x, tid = threadIdx.x;
    float s = 0.f;
    const float* p = xf + bc*HW;
    for (int i = tid; i < HW; i += 256) s += p[i];
    red[tid] = s; __syncthreads();
    for (int st = 128; st > 0; st >>= 1) {
        if (tid < st) red[tid] += red[tid + st];
        __syncthreads();
    }
    if (tid == 0) g_pool[bc] = red[0] * (1.f/HW);
}

// ---------------- 5) channel-filter MLP ---------------------------------------
__global__ void ch_kernel(const float* __restrict__ ch_w1, const float* __restrict__ ch_b1,
                          const float* __restrict__ ch_w2, const float* __restrict__ ch_b2)
{
    int t = threadIdx.x;
    if (t >= 64) return;
    int b = t >> 4, s = t & 15;
    float h1[4];
    #pragma unroll
    for (int m = 0; m < 4; m++) {
        float a = ch_b1[s*4 + m];
        #pragma unroll
        for (int c = 0; c < 3; c++) a = fmaf(g_pool[b*3 + c], ch_w1[(s*4 + m)*3 + c], a);
        h1[m] = fmaxf(a, 0.f);
    }
    for (int k = 0; k < 27; k++) {
        float a = ch_b2[s*27 + k];
        #pragma unroll
        for (int m = 0; m < 4; m++) a = fmaf(h1[m], ch_w2[(s*27 + k)*4 + m], a);
        g_ch[(b*16 + s)*27 + k] = a;
    }
}

// ---------------- 6) DDF up: f32x2 s-pair packed, 2 threads/px ----------------
__global__ __launch_bounds__(256) void ddf_kernel(
    const float* __restrict__ spw, const float* __restrict__ spb,
    float* __restrict__ out)
{
    __shared__ __align__(16) float2 sSpw2[8*9*28];   // [i][k][j] pairs (s=2i, 2i+1)
    __shared__ float2 sSpb2[72];                      // [i][k]
    __shared__ float2 sCh2[216];                      // [i][j=c*9+k]
    __shared__ float sX[3*3*132];                     // 3ch x 3rows x 132 cols

    int tid = threadIdx.x;
    int b = blockIdx.y, y = blockIdx.x;

    for (int idx = tid; idx < 2016; idx += 256) {
        int i = idx / 252, rem = idx - i*252;
        int k = rem / 28, j = rem - k*28;
        float v0 = 0.f, v1 = 0.f;
        if (j < 27) {
            v0 = spw[((2*i  )*9 + k)*27 + j];
            v1 = spw[((2*i+1)*9 + k)*27 + j];
        }
        sSpw2[idx] = make_float2(v0, v1);
    }
    if (tid < 72) {
        int i = tid / 9, k = tid - i*9;
        sSpb2[tid] = make_float2(spb[(2*i)*9 + k], spb[(2*i+1)*9 + k]);
    }
    if (tid < 216) {
        int i = tid / 27, j = tid - i*27;
        sCh2[tid] = make_float2(g_ch[b*432 + (2*i)*27 + j],
                                g_ch[b*432 + (2*i+1)*27 + j]);
    }
    if (tid < 9) {
        float* row = sX + tid*132;
        row[0] = 0.f; row[129] = 0.f; row[130] = 0.f; row[131] = 0.f;
    }
    for (int idx = tid; idx < 288; idx += 256) {
        int row9 = idx >> 5, q = idx & 31;
        int c = row9 / 3, r = row9 - c*3;
        int gy = y - 1 + r;
        float4 v = make_float4(0.f, 0.f, 0.f, 0.f);
        if (gy >= 0 && gy < 128)
            v = *(const float4*)(g_xfin + (b*3 + c)*HW + gy*128 + q*4);
        float* dst = sX + row9*132 + 1 + q*4;
        dst[0] = v.x; dst[1] = v.y; dst[2] = v.z; dst[3] = v.w;
    }
    __syncthreads();

    int px = tid & 127, half = tid >> 7;

    ull winD[28];
    #pragma unroll
    for (int c = 0; c < 3; c++)
        #pragma unroll
        for (int r = 0; r < 3; r++)
            #pragma unroll
            for (int q = 0; q < 3; q++)
                winD[c*9 + r*3 + q] = dup2(sX[(c*3 + r)*132 + px + q]);
    winD[27] = 0ull;

    float* ob = out + b*3*(512*512);
    int i0 = half*4;
    #pragma unroll 1
    for (int i = i0; i < i0 + 4; i++) {
        ull a0 = 0ull, a1 = 0ull, a2 = 0ull;
        #pragma unroll
        for (int k = 0; k < 9; k++) {
            ull spv = *(const ull*)&sSpb2[i*9 + k];
            const ulonglong2* w2 = (const ulonglong2*)(sSpw2 + (i*9 + k)*28);
            #pragma unroll
            for (int j2 = 0; j2 < 14; j2++) {
                ulonglong2 w = w2[j2];
                ffma2(spv, w.x, winD[j2*2]);
                ffma2(spv, w.y, winD[j2*2 + 1]);
            }
            ull t0 = add2(*(const ull*)&sCh2[i*27 + k],      spv);
            ull t1 = add2(*(const ull*)&sCh2[i*27 + 9 + k],  spv);
            ull t2 = add2(*(const ull*)&sCh2[i*27 + 18 + k], spv);
            ffma2(a0, winD[k],      t0);
            ffma2(a1, winD[9 + k],  t1);
            ffma2(a2, winD[18 + k], t2);
        }
        float2 r0 = unpk(a0), r1 = unpk(a1), r2 = unpk(a2);
        int s0 = 2*i, s1 = 2*i + 1;
        int oy0 = (y << 2) + (s0 >> 2), ox0 = (px << 2) + (s0 & 3);
        int oy1 = (y << 2) + (s1 >> 2), ox1 = (px << 2) + (s1 & 3);
        ob[0*262144 + oy0*512 + ox0] = fminf(fmaxf(r0.x, 0.f), 255.f);
        ob[1*262144 + oy0*512 + ox0] = fminf(fmaxf(r1.x, 0.f), 255.f);
        ob[2*262144 + oy0*512 + ox0] = fminf(fmaxf(r2.x, 0.f), 255.f);
        ob[0*262144 + oy1*512 + ox1] = fminf(fmaxf(r0.y, 0.f), 255.f);
        ob[1*262144 + oy1*512 + ox1] = fminf(fmaxf(r1.y, 0.f), 255.f);
        ob[2*262144 + oy1*512 + ox1] = fminf(fmaxf(r2.y, 0.f), 255.f);
    }
}

// ---------------- host orchestration ------------------------------------------
extern "C" void kernel_launch(void* const* d_in, const int* in_sizes, int n_in,
                              void* d_out, int out_size)
{
    const float* X      = (const float*)d_in[0];
    const float* lstm_w = (const float*)d_in[1];
    const float* lstm_b = (const float*)d_in[2];
    const float* dw[3][6];
    for (int i = 0; i < 3; i++)
        for (int j = 0; j < 6; j++)
            dw[i][j] = (const float*)d_in[3 + i*6 + j];   // ow, ob, mw, mb, w, b
    const float* conv_w = (const float*)d_in[21];
    const float* conv_b = (const float*)d_in[22];
    const float* sp_w   = (const float*)d_in[23];
    const float* sp_b   = (const float*)d_in[24];
    const float* ch_w1  = (const float*)d_in[25];
    const float* ch_b1  = (const float*)d_in[26];
    const float* ch_w2  = (const float*)d_in[27];
    const float* ch_b2  = (const float*)d_in[28];

    float* out_main = (float*)d_out;                     // [4,3,512,512]
    float* hid      = out_main + 4*3*512*512;            // [4,64,128,128]
    float* cell     = hid + 4*64*128*128;                // [4,64,128,128]

    void *pxb0, *pxb1, *poff, *pmask, *pxfin;
    cudaGetSymbolAddress(&pxb0, g_xbuf0);
    cudaGetSymbolAddress(&pxb1, g_xbuf1);
    cudaGetSymbolAddress(&poff,  g_off);
    cudaGetSymbolAddress(&pmask, g_mask);
    cudaGetSymbolAddress(&pxfin, g_xfin);
    float* xb0 = (float*)pxb0;
    float* xb1 = (float*)pxb1;
    float* off_p  = (float*)poff;
    float* mask_p = (float*)pmask;
    float* xfin_p = (float*)pxfin;

    cudaFuncSetAttribute(deform_kernel, cudaFuncAttributeMaxDynamicSharedMemorySize,
                         DF_SMEM_BYTES);

    dim3 rowGrid(128, B_);
    dim3 convGrid(4, 16, B_);

    shift_kernel<<<1, 32>>>();                 // shifts ncu -s 5 onto deform stage 2

    lstm_kernel<<<rowGrid, 256>>>(X, lstm_w, lstm_b, hid, cell);

    conv_off_kernel<<<rowGrid, 256>>>(hid, X, dw[0][0], dw[0][1],
                                      dw[0][2], dw[0][3], off_p, mask_p);
    deform_kernel<<<rowGrid, 256, DF_SMEM_BYTES>>>(hid, X, dw[0][4], dw[0][5], xb0);

    conv_off_kernel<<<rowGrid, 256>>>(xb0, X, dw[1][0], dw[1][1],
                                      dw[1][2], dw[1][3], off_p, mask_p);
    deform_kernel<<<rowGrid, 256, DF_SMEM_BYTES>>>(xb0, X, dw[1][4], dw[1][5], xb1);

    conv_off_kernel<<<rowGrid, 256>>>(xb1, X, dw[2][0], dw[2][1],
                                      dw[2][2], dw[2][3], off_p, mask_p);
    deform_kernel<<<rowGrid, 256, DF_SMEM_BYTES>>>(xb1, X, dw[2][4], dw[2][5], xb0);

    conv_small_kernel<3><<<convGrid, 256>>>(xb0, X, conv_w, conv_b, xfin_p);

    pool_kernel<<<B_*3, 256>>>(xfin_p);
    ch_kernel<<<1, 64>>>(ch_w1, ch_b1, ch_w2, ch_b2);
    ddf_kernel<<<rowGrid, 256>>>(sp_w, sp_b, out_main);
}

// round 11
// speedup vs baseline: 1.8920x; 1.0242x over previous
#include <cuda_runtime.h>
#include <math.h>

#define HW   16384
#define B_   4
#define NCH  67

// ---------------- scratch ------------------------------------------------------
__device__ float g_xcat0[B_*NCH*HW];
__device__ float g_xcat1[B_*NCH*HW];
__device__ float g_off  [B_*18*HW];
__device__ float g_mask [B_*9*HW];
__device__ float g_xfin [B_*3*HW];
__device__ float g_ch   [B_*16*27];
__device__ float g_pool [B_*3];

__device__ __forceinline__ float sigm(float v){ return 1.f/(1.f+__expf(-v)); }

// ---- packed fp32x2 helpers ----------------------------------------------------
typedef unsigned long long ull;
__device__ __forceinline__ ull dup2(float v){
    ull r; asm("mov.b64 %0, {%1, %1};" : "=l"(r) : "f"(v)); return r;
}
__device__ __forceinline__ void ffma2(ull &d, ull a, ull b){
    asm("fma.rn.f32x2 %0, %1, %2, %0;" : "+l"(d) : "l"(a), "l"(b));
}
__device__ __forceinline__ ull add2(ull a, ull b){
    ull r; asm("add.rn.f32x2 %0, %1, %2;" : "=l"(r) : "l"(a), "l"(b)); return r;
}
__device__ __forceinline__ float2 unpk(ull v){
    float2 f; asm("mov.b64 {%0, %1}, %2;" : "=f"(f.x), "=f"(f.y) : "l"(v)); return f;
}

// ---------------- 0) copy LR into both xcat buffers (also shifts ncu index) ---
__global__ void copy_lr_kernel(const float* __restrict__ X)
{
    int i = blockIdx.x*256 + threadIdx.x;          // over B*3*HW/4 float4s
    if (i >= B_*3*HW/4) return;
    int b = i / (3*HW/4), rem = i - b*(3*HW/4);
    float4 v = ((const float4*)X)[i];
    ((float4*)(g_xcat0 + (b*NCH + 64)*HW))[rem] = v;
    ((float4*)(g_xcat1 + (b*NCH + 64)*HW))[rem] = v;
}

// ---------------- 1) ConvLSTM: row-CTA, smem-staged, f32x2 k-pairs ------------
__global__ __launch_bounds__(256) void lstm_kernel(
    const float* __restrict__ X, const float* __restrict__ w,
    const float* __restrict__ bias,
    float* __restrict__ hid, float* __restrict__ cell, float* __restrict__ xcat)
{
    __shared__ float sX[9*132];
    __shared__ float2 sW2[32*3*28];
    __shared__ float2 sB2[32*3];

    int tid = threadIdx.x;
    int b = blockIdx.y, y = blockIdx.x;

    for (int i = tid; i < 2688; i += 256) {
        int kp = i / 84, rem = i - kp*84;
        int g = rem / 28, t = rem - g*28;
        int gbase = (g == 0) ? 0 : (g == 1) ? 128 : 192;
        float v0 = 0.f, v1 = 0.f;
        if (t < 27) {
            v0 = w[(gbase + 2*kp    )*603 + t];
            v1 = w[(gbase + 2*kp + 1)*603 + t];
        }
        sW2[i] = make_float2(v0, v1);
    }
    if (tid < 96) {
        int kp = tid / 3, g = tid - kp*3;
        int gbase = (g == 0) ? 0 : (g == 1) ? 128 : 192;
        sB2[tid] = make_float2(bias[gbase + 2*kp], bias[gbase + 2*kp + 1]);
    }
    if (tid < 9) {
        float* row = sX + tid*132;
        row[0] = 0.f; row[129] = 0.f; row[130] = 0.f; row[131] = 0.f;
    }
    for (int idx = tid; idx < 288; idx += 256) {
        int row9 = idx >> 5, q = idx & 31;
        int c = row9 / 3, r = row9 - c*3;
        int gy = y - 1 + r;
        float4 v = make_float4(0.f, 0.f, 0.f, 0.f);
        if (gy >= 0 && gy < 128)
            v = *(const float4*)(X + (b*3 + c)*HW + gy*128 + q*4);
        float* dst = sX + row9*132 + 1 + q*4;
        dst[0] = v.x; dst[1] = v.y; dst[2] = v.z; dst[3] = v.w;
    }
    __syncthreads();

    int px = tid & 127, kh = tid >> 7;

    ull win[28];
    #pragma unroll
    for (int c = 0; c < 3; c++)
        #pragma unroll
        for (int r = 0; r < 3; r++)
            #pragma unroll
            for (int q = 0; q < 3; q++)
                win[c*9 + r*3 + q] = dup2(sX[(c*3 + r)*132 + px + q]);
    win[27] = 0ull;

    int pix = y*128 + px;
    int kp0 = kh*16;
    #pragma unroll 1
    for (int kp = kp0; kp < kp0 + 16; kp++) {
        ull aI = *(const ull*)&sB2[kp*3 + 0];
        ull aO = *(const ull*)&sB2[kp*3 + 1];
        ull aG = *(const ull*)&sB2[kp*3 + 2];
        const ulonglong2* wI = (const ulonglong2*)(sW2 + (kp*3 + 0)*28);
        const ulonglong2* wO = (const ulonglong2*)(sW2 + (kp*3 + 1)*28);
        const ulonglong2* wG = (const ulonglong2*)(sW2 + (kp*3 + 2)*28);
        #pragma unroll
        for (int t2 = 0; t2 < 14; t2++) {
            ulonglong2 wi = wI[t2];
            ffma2(aI, wi.x, win[2*t2]); ffma2(aI, wi.y, win[2*t2 + 1]);
            ulonglong2 wo = wO[t2];
            ffma2(aO, wo.x, win[2*t2]); ffma2(aO, wo.y, win[2*t2 + 1]);
            ulonglong2 wg = wG[t2];
            ffma2(aG, wg.x, win[2*t2]); ffma2(aG, wg.y, win[2*t2 + 1]);
        }
        float2 ai = unpk(aI), ao = unpk(aO), ag = unpk(aG);
        float c0 = sigm(ai.x)*tanhf(ag.x);
        float c1 = sigm(ai.y)*tanhf(ag.y);
        float h0 = sigm(ao.x)*tanhf(c0);
        float h1 = sigm(ao.y)*tanhf(c1);
        int k0 = 2*kp;
        hid [(b*64 + k0    )*HW + pix] = h0;
        hid [(b*64 + k0 + 1)*HW + pix] = h1;
        cell[(b*64 + k0    )*HW + pix] = c0;
        cell[(b*64 + k0 + 1)*HW + pix] = c1;
        xcat[(b*NCH + k0    )*HW + pix] = h0;
        xcat[(b*NCH + k0 + 1)*HW + pix] = h1;
    }
}

// ---------------- 2) offset/mask conv, f32x2 packed GEMM ----------------------
__global__ __launch_bounds__(256) void conv_off_kernel(
    const float* __restrict__ xcat,
    const float* __restrict__ w0, const float* __restrict__ b0,
    const float* __restrict__ w1, const float* __restrict__ b1,
    float* __restrict__ out0, float* __restrict__ out1)
{
    __shared__ float sTile[16*3*132];
    __shared__ float sW[144*32];

    int tid = threadIdx.x;
    int pg = tid & 31;
    int og = tid >> 5;
    int b = blockIdx.y, y = blockIdx.x;
    int y0 = y - 1;

    ull acc[2][4];
    #pragma unroll
    for (int q = 0; q < 2; q++)
        #pragma unroll
        for (int p = 0; p < 4; p++) acc[q][p] = 0ull;

    for (int c0 = 0; c0 < 67; c0 += 16) {
        int cnt = (67 - c0) < 16 ? (67 - c0) : 16;
        for (int i = tid; i < cnt*3; i += 256) {
            int c = i / 3, r = i - c*3;
            float* row = sTile + c*396 + r*132;
            row[0] = 0.f; row[129] = 0.f; row[130] = 0.f; row[131] = 0.f;
        }
        for (int i = tid; i < cnt*96; i += 256) {
            int c = i / 96, rem = i - c*96;
            int r = rem >> 5, q = rem & 31;
            int gy = y0 + r;
            const float* src = xcat + (b*NCH + c0 + c)*HW;
            float4 v = make_float4(0.f, 0.f, 0.f, 0.f);
            if (gy >= 0 && gy < 128) v = *(const float4*)(src + gy*128 + q*4);
            float* dst = sTile + c*396 + r*132 + 1 + q*4;
            dst[0] = v.x; dst[1] = v.y; dst[2] = v.z; dst[3] = v.w;
        }
        int c09 = c0*9;
        for (int i = tid; i < cnt*288; i += 256) {
            int o = i & 31, tdx = i >> 5;
            float wv = 0.f;
            if (o < 18)      wv = w0[o*603 + c09 + tdx];
            else if (o < 27) wv = w1[(o-18)*603 + c09 + tdx];
            sW[tdx*32 + o] = wv;
        }
        __syncthreads();

        for (int c = 0; c < cnt; c++) {
            #pragma unroll
            for (int ky = 0; ky < 3; ky++) {
                const float* rb = sTile + c*396 + ky*132 + pg*4;
                float4 a4 = *(const float4*)rb;
                float2 a2 = *(const float2*)(rb + 4);
                ull vv[6];
                vv[0] = dup2(a4.x); vv[1] = dup2(a4.y); vv[2] = dup2(a4.z);
                vv[3] = dup2(a4.w); vv[4] = dup2(a2.x); vv[5] = dup2(a2.y);
                #pragma unroll
                for (int kx = 0; kx < 3; kx++) {
                    ulonglong2 w = *(const ulonglong2*)(sW + (c*9 + ky*3 + kx)*32 + og*4);
                    #pragma unroll
                    for (int p = 0; p < 4; p++) {
                        ffma2(acc[0][p], w.x, vv[kx + p]);
                        ffma2(acc[1][p], w.y, vv[kx + p]);
                    }
                }
            }
        }
        __syncthreads();
    }

    int pixb = y*128 + pg*4;
    #pragma unroll
    for (int wp = 0; wp < 2; wp++) {
        int o0 = og*4 + 2*wp;
        float2 a0 = unpk(acc[wp][0]), a1 = unpk(acc[wp][1]);
        float2 a2 = unpk(acc[wp][2]), a3 = unpk(acc[wp][3]);
        if (o0 < 18) {
            float bb = b0[o0];
            *(float4*)(out0 + (b*18 + o0)*HW + pixb) =
                make_float4(a0.x+bb, a1.x+bb, a2.x+bb, a3.x+bb);
        } else if (o0 < 27) {
            float bb = b1[o0-18];
            *(float4*)(out1 + (b*9 + (o0-18))*HW + pixb) =
                make_float4(2.f*sigm(a0.x+bb), 2.f*sigm(a1.x+bb),
                            2.f*sigm(a2.x+bb), 2.f*sigm(a3.x+bb));
        }
        int o1 = o0 + 1;
        if (o1 < 18) {
            float bb = b0[o1];
            *(float4*)(out0 + (b*18 + o1)*HW + pixb) =
                make_float4(a0.y+bb, a1.y+bb, a2.y+bb, a3.y+bb);
        } else if (o1 < 27) {
            float bb = b1[o1-18];
            *(float4*)(out1 + (b*9 + (o1-18))*HW + pixb) =
                make_float4(2.f*sigm(a0.y+bb), 2.f*sigm(a1.y+bb),
                            2.f*sigm(a2.y+bb), 2.f*sigm(a3.y+bb));
        }
    }
}

// ---------------- 2b) small direct conv (final 3-out fuse conv) ---------------
template<int COUT>
__global__ __launch_bounds__(256) void conv_small_kernel(
    const float* __restrict__ xcat,
    const float* __restrict__ w0, const float* __restrict__ b0,
    float* __restrict__ out0)
{
    __shared__ float sT[16*10*34];
    __shared__ float sW[COUT*16*9];
    int tid = threadIdx.x;
    int tx = tid & 31, ty = tid >> 5;
    int b = blockIdx.z;
    int x = blockIdx.x*32 + tx, y = blockIdx.y*8 + ty;
    int gx0 = blockIdx.x*32 - 1, gy0 = blockIdx.y*8 - 1;

    float acc[COUT];
    #pragma unroll
    for (int o = 0; o < COUT; o++) acc[o] = 0.f;

    for (int c0 = 0; c0 < 67; c0 += 16) {
        int cnt = (67 - c0) < 16 ? (67 - c0) : 16;
        for (int i = tid; i < cnt*340; i += 256) {
            int c = i / 340, rem = i - c*340;
            int r = rem / 34, col = rem - r*34;
            int gy = gy0 + r, gx = gx0 + col;
            const float* src = xcat + (b*NCH + c0 + c)*HW;
            sT[i] = (gy >= 0 && gy < 128 && gx >= 0 && gx < 128)
                  ? src[gy*128 + gx] : 0.f;
        }
        int wtot = COUT*cnt*9;
        for (int i = tid; i < wtot; i += 256) {
            int o = i / (cnt*9), rem = i - o*(cnt*9);
            sW[o*144 + rem] = w0[o*603 + c0*9 + rem];
        }
        __syncthreads();
        for (int c = 0; c < cnt; c++) {
            float win[9];
            #pragma unroll
            for (int r = 0; r < 3; r++)
                #pragma unroll
                for (int q = 0; q < 3; q++)
                    win[r*3+q] = sT[c*340 + (ty+r)*34 + (tx+q)];
            #pragma unroll
            for (int o = 0; o < COUT; o++) {
                #pragma unroll
                for (int t = 0; t < 9; t++)
                    acc[o] = fmaf(sW[o*144 + c*9 + t], win[t], acc[o]);
            }
        }
        __syncthreads();
    }
    int pix = y*128 + x;
    #pragma unroll
    for (int o = 0; o < COUT; o++)
        out0[(b*COUT + o)*HW + pix] = acc[o] + b0[o];
}

// ---------------- 3) deform: group-gather + 64x603 GEMM, f32x2 ----------------
#define DF_SIDX  4608
#define DF_SV    (4608 + 1152)
#define DF_SWC   (DF_SV + 67*132)
#define DF_SMEM_BYTES ((DF_SWC + 67*64) * 4)

__global__ __launch_bounds__(256, 3) void deform_kernel(
    const float* __restrict__ xcat,
    const float* __restrict__ wmain, const float* __restrict__ bias,
    float* __restrict__ out)
{
    extern __shared__ float smem[];
    float4* sWt = (float4*)smem;                 // [k][128 px] corner weights
    int*    sIdx= (int*)(smem + DF_SIDX);
    float*  sV  = smem + DF_SV;                  // [j][px], stride 132
    float*  sWc = smem + DF_SWC;                 // [j][64 outs]

    int tid = threadIdx.x;
    int b = blockIdx.y, y = blockIdx.x;

    // ---- Phase A: bilinear meta (9 taps x 128 px) ----
    for (int e = tid; e < 1152; e += 256) {
        int p = e & 127, k = e >> 7;
        int pix = y*128 + p;
        float offy = g_off [(b*18 + 2*k    )*HW + pix];
        float offx = g_off [(b*18 + 2*k + 1)*HW + pix];
        float m    = g_mask[(b*9  + k      )*HW + pix];
        int ky = k / 3, kx = k - ky*3;
        float py = (float)(y + ky - 1) + offy;
        float px = (float)(p + kx - 1) + offx;
        float fy = floorf(py), fx = floorf(px);
        float wy = py - fy,    wx = px - fx;
        int iy = (int)fy, ix = (int)fx;
        bool vy0 = (iy   >= 0 && iy   <= 127);
        bool vy1 = (iy+1 >= 0 && iy+1 <= 127);
        bool vx0 = (ix   >= 0 && ix   <= 127);
        bool vx1 = (ix+1 >= 0 && ix+1 <= 127);
        float4 wv;
        wv.x = (1.f-wy)*(1.f-wx)*m * ((vy0 && vx0) ? 1.f : 0.f);
        wv.y = (1.f-wy)*wx      *m * ((vy0 && vx1) ? 1.f : 0.f);
        wv.z = wy*(1.f-wx)      *m * ((vy1 && vx0) ? 1.f : 0.f);
        wv.w = wy*wx            *m * ((vy1 && vx1) ? 1.f : 0.f);
        sWt[e] = wv;
        int iy0 = min(max(iy,   0), 127), iy1 = min(max(iy+1, 0), 127);
        int ix0 = min(max(ix,   0), 127), ix1 = min(max(ix+1, 0), 127);
        sIdx[e] = iy0 | (iy1 << 8) | (ix0 << 16) | (ix1 << 24);
    }
    __syncthreads();

    const float* xb = xcat + b*NCH*HW;
    int pg = tid & 31, og = tid >> 5;

    ull acc[4][4];
    #pragma unroll
    for (int q = 0; q < 4; q++)
        #pragma unroll
        for (int p = 0; p < 4; p++) acc[q][p] = 0ull;

    for (int c0 = 0; c0 < 603; c0 += 67) {
        // stage weight chunk transposed
        for (int i = tid; i < 67*64; i += 256) {
            int o = i & 63, j = i >> 6;
            sWc[j*64 + o] = wmain[o*603 + c0 + j];
        }
        // group gather: one (tap,pixel) group -> all its channels in the chunk
        int c0m9 = c0 % 9;
        for (int g = tid; g < 1152; g += 256) {
            int p = g & 127, k = g >> 7;
            float4 wt = sWt[g];
            int pk = sIdx[g];
            int iy0 =  pk        & 255, iy1 = (pk >> 8)  & 255;
            int ix0 = (pk >> 16) & 255, ix1 = (pk >> 24) & 255;
            int j0 = k - c0m9; if (j0 < 0) j0 += 9;
            int n = (j0 < 4) ? 8 : 7;                 // chunk size 67, 9 taps
            int cb = ((c0 + j0) / 9) * HW;
            int i0 = cb + iy0*128 + ix0;
            int i1 = cb + iy0*128 + ix1;
            int i2 = cb + iy1*128 + ix0;
            int i3 = cb + iy1*128 + ix1;
            float* sv = sV + j0*132 + p;
            #pragma unroll 1
            for (int it = 0; it < n; it++) {
                float val = wt.x * __ldg(xb + i0) + wt.y * __ldg(xb + i1)
                          + wt.z * __ldg(xb + i2) + wt.w * __ldg(xb + i3);
                *sv = val;
                i0 += HW; i1 += HW; i2 += HW; i3 += HW;
                sv += 9*132;
            }
        }
        __syncthreads();

        const float* vp = sV + pg*4;
        const float* wp_ = sWc + og*8;
        #pragma unroll 4
        for (int j = 0; j < 67; j++) {
            ulonglong2 wA = *(const ulonglong2*)(wp_ + j*64);
            ulonglong2 wB = *(const ulonglong2*)(wp_ + j*64 + 4);
            float4 v = *(const float4*)(vp + j*132);
            ull v0 = dup2(v.x), v1 = dup2(v.y), v2 = dup2(v.z), v3 = dup2(v.w);
            ffma2(acc[0][0], wA.x, v0); ffma2(acc[0][1], wA.x, v1);
            ffma2(acc[0][2], wA.x, v2); ffma2(acc[0][3], wA.x, v3);
            ffma2(acc[1][0], wA.y, v0); ffma2(acc[1][1], wA.y, v1);
            ffma2(acc[1][2], wA.y, v2); ffma2(acc[1][3], wA.y, v3);
            ffma2(acc[2][0], wB.x, v0); ffma2(acc[2][1], wB.x, v1);
            ffma2(acc[2][2], wB.x, v2); ffma2(acc[2][3], wB.x, v3);
            ffma2(acc[3][0], wB.y, v0); ffma2(acc[3][1], wB.y, v1);
            ffma2(acc[3][2], wB.y, v2); ffma2(acc[3][3], wB.y, v3);
        }
        __syncthreads();
    }

    int pixb = y*128 + pg*4;
    #pragma unroll
    for (int wp = 0; wp < 4; wp++) {
        int o0 = og*8 + 2*wp;
        float2 a0 = unpk(acc[wp][0]), a1 = unpk(acc[wp][1]);
        float2 a2 = unpk(acc[wp][2]), a3 = unpk(acc[wp][3]);
        float bb0 = bias[o0], bb1 = bias[o0+1];
        *(float4*)(out + (b*NCH + o0)*HW + pixb) =
            make_float4(a0.x+bb0, a1.x+bb0, a2.x+bb0, a3.x+bb0);
        *(float4*)(out + (b*NCH + o0+1)*HW + pixb) =
            make_float4(a0.y+bb1, a1.y+bb1, a2.y+bb1, a3.y+bb1);
    }
}

// ---------------- 4) global average pool --------------------------------------
__global__ void pool_kernel(const float* __restrict__ xf)
{
    __shared__ float red[256];
    int bc = blockIdx.x, tid = threadIdx.x;
    float s = 0.f;
    const float* p = xf + bc*HW;
    for (int i = tid; i < HW; i += 256) s += p[i];
    red[tid] = s; __syncthreads();
    for (int st = 128; st > 0; st >>= 1) {
        if (tid < st) red[tid] += red[tid + st];
        __syncthreads();
    }
    if (tid == 0) g_pool[bc] = red[0] * (1.f/HW);
}

// ---------------- 5) channel-filter MLP ---------------------------------------
__global__ void ch_kernel(const float* __restrict__ ch_w1, const float* __restrict__ ch_b1,
                          const float* __restrict__ ch_w2, const float* __restrict__ ch_b2)
{
    int t = threadIdx.x;
    if (t >= 64) return;
    int b = t >> 4, s = t & 15;
    float h1[4];
    #pragma unroll
    for (int m = 0; m < 4; m++) {
        float a = ch_b1[s*4 + m];
        #pragma unroll
        for (int c = 0; c < 3; c++) a = fmaf(g_pool[b*3 + c], ch_w1[(s*4 + m)*3 + c], a);
        h1[m] = fmaxf(a, 0.f);
    }
    for (int k = 0; k < 27; k++) {
        float a = ch_b2[s*27 + k];
        #pragma unroll
        for (int m = 0; m < 4; m++) a = fmaf(h1[m], ch_w2[(s*27 + k)*4 + m], a);
        g_ch[(b*16 + s)*27 + k] = a;
    }
}

// ---------------- 6) DDF up: f32x2 s-pair packed, 2 threads/px ----------------
__global__ __launch_bounds__(256) void ddf_kernel(
    const float* __restrict__ spw, const float* __restrict__ spb,
    float* __restrict__ out)
{
    __shared__ __align__(16) float2 sSpw2[8*9*28];
    __shared__ float2 sSpb2[72];
    __shared__ float2 sCh2[216];
    __shared__ float sX[3*3*132];

    int tid = threadIdx.x;
    int b = blockIdx.y, y = blockIdx.x;

    for (int idx = tid; idx < 2016; idx += 256) {
        int i = idx / 252, rem = idx - i*252;
        int k = rem / 28, j = rem - k*28;
        float v0 = 0.f, v1 = 0.f;
        if (j < 27) {
            v0 = spw[((2*i  )*9 + k)*27 + j];
            v1 = spw[((2*i+1)*9 + k)*27 + j];
        }
        sSpw2[idx] = make_float2(v0, v1);
    }
    if (tid < 72) {
        int i = tid / 9, k = tid - i*9;
        sSpb2[tid] = make_float2(spb[(2*i)*9 + k], spb[(2*i+1)*9 + k]);
    }
    if (tid < 216) {
        int i = tid / 27, j = tid - i*27;
        sCh2[tid] = make_float2(g_ch[b*432 + (2*i)*27 + j],
                                g_ch[b*432 + (2*i+1)*27 + j]);
    }
    if (tid < 9) {
        float* row = sX + tid*132;
        row[0] = 0.f; row[129] = 0.f; row[130] = 0.f; row[131] = 0.f;
    }
    for (int idx = tid; idx < 288; idx += 256) {
        int row9 = idx >> 5, q = idx & 31;
        int c = row9 / 3, r = row9 - c*3;
        int gy = y - 1 + r;
        float4 v = make_float4(0.f, 0.f, 0.f, 0.f);
        if (gy >= 0 && gy < 128)
            v = *(const float4*)(g_xfin + (b*3 + c)*HW + gy*128 + q*4);
        float* dst = sX + row9*132 + 1 + q*4;
        dst[0] = v.x; dst[1] = v.y; dst[2] = v.z; dst[3] = v.w;
    }
    __syncthreads();

    int px = tid & 127, half = tid >> 7;

    ull winD[28];
    #pragma unroll
    for (int c = 0; c < 3; c++)
        #pragma unroll
        for (int r = 0; r < 3; r++)
            #pragma unroll
            for (int q = 0; q < 3; q++)
                winD[c*9 + r*3 + q] = dup2(sX[(c*3 + r)*132 + px + q]);
    winD[27] = 0ull;

    float* ob = out + b*3*(512*512);
    int i0 = half*4;
    #pragma unroll 1
    for (int i = i0; i < i0 + 4; i++) {
        ull a0 = 0ull, a1 = 0ull, a2 = 0ull;
        #pragma unroll
        for (int k = 0; k < 9; k++) {
            ull spv = *(const ull*)&sSpb2[i*9 + k];
            const ulonglong2* w2 = (const ulonglong2*)(sSpw2 + (i*9 + k)*28);
            #pragma unroll
            for (int j2 = 0; j2 < 14; j2++) {
                ulonglong2 w = w2[j2];
                ffma2(spv, w.x, winD[j2*2]);
                ffma2(spv, w.y, winD[j2*2 + 1]);
            }
            ull t0 = add2(*(const ull*)&sCh2[i*27 + k],      spv);
            ull t1 = add2(*(const ull*)&sCh2[i*27 + 9 + k],  spv);
            ull t2 = add2(*(const ull*)&sCh2[i*27 + 18 + k], spv);
            ffma2(a0, winD[k],      t0);
            ffma2(a1, winD[9 + k],  t1);
            ffma2(a2, winD[18 + k], t2);
        }
        float2 r0 = unpk(a0), r1 = unpk(a1), r2 = unpk(a2);
        int s0 = 2*i, s1 = 2*i + 1;
        int oy0 = (y << 2) + (s0 >> 2), ox0 = (px << 2) + (s0 & 3);
        int oy1 = (y << 2) + (s1 >> 2), ox1 = (px << 2) + (s1 & 3);
        ob[0*262144 + oy0*512 + ox0] = fminf(fmaxf(r0.x, 0.f), 255.f);
        ob[1*262144 + oy0*512 + ox0] = fminf(fmaxf(r1.x, 0.f), 255.f);
        ob[2*262144 + oy0*512 + ox0] = fminf(fmaxf(r2.x, 0.f), 255.f);
        ob[0*262144 + oy1*512 + ox1] = fminf(fmaxf(r0.y, 0.f), 255.f);
        ob[1*262144 + oy1*512 + ox1] = fminf(fmaxf(r1.y, 0.f), 255.f);
        ob[2*262144 + oy1*512 + ox1] = fminf(fmaxf(r2.y, 0.f), 255.f);
    }
}

// ---------------- host orchestration ------------------------------------------
extern "C" void kernel_launch(void* const* d_in, const int* in_sizes, int n_in,
                              void* d_out, int out_size)
{
    const float* X      = (const float*)d_in[0];
    const float* lstm_w = (const float*)d_in[1];
    const float* lstm_b = (const float*)d_in[2];
    const float* dw[3][6];
    for (int i = 0; i < 3; i++)
        for (int j = 0; j < 6; j++)
            dw[i][j] = (const float*)d_in[3 + i*6 + j];   // ow, ob, mw, mb, w, b
    const float* conv_w = (const float*)d_in[21];
    const float* conv_b = (const float*)d_in[22];
    const float* sp_w   = (const float*)d_in[23];
    const float* sp_b   = (const float*)d_in[24];
    const float* ch_w1  = (const float*)d_in[25];
    const float* ch_b1  = (const float*)d_in[26];
    const float* ch_w2  = (const float*)d_in[27];
    const float* ch_b2  = (const float*)d_in[28];

    float* out_main = (float*)d_out;                     // [4,3,512,512]
    float* hid      = out_main + 4*3*512*512;            // [4,64,128,128]
    float* cell     = hid + 4*64*128*128;                // [4,64,128,128]

    void *pxc0, *pxc1, *poff, *pmask, *pxfin;
    cudaGetSymbolAddress(&pxc0, g_xcat0);
    cudaGetSymbolAddress(&pxc1, g_xcat1);
    cudaGetSymbolAddress(&poff,  g_off);
    cudaGetSymbolAddress(&pmask, g_mask);
    cudaGetSymbolAddress(&pxfin, g_xfin);
    float* xc0 = (float*)pxc0;
    float* xc1 = (float*)pxc1;
    float* off_p  = (float*)poff;
    float* mask_p = (float*)pmask;
    float* xfin_p = (float*)pxfin;

    cudaFuncSetAttribute(deform_kernel, cudaFuncAttributeMaxDynamicSharedMemorySize,
                         DF_SMEM_BYTES);

    dim3 rowGrid(128, B_);
    dim3 convGrid(4, 16, B_);

    copy_lr_kernel<<<(B_*3*HW/4 + 255)/256, 256>>>(X);          // launch 0

    lstm_kernel<<<rowGrid, 256>>>(X, lstm_w, lstm_b, hid, cell, xc0);   // 1

    conv_off_kernel<<<rowGrid, 256>>>(xc0, dw[0][0], dw[0][1],
                                      dw[0][2], dw[0][3], off_p, mask_p);  // 2
    deform_kernel<<<rowGrid, 256, DF_SMEM_BYTES>>>(xc0, dw[0][4], dw[0][5], xc1); // 3

    conv_off_kernel<<<rowGrid, 256>>>(xc1, dw[1][0], dw[1][1],
                                      dw[1][2], dw[1][3], off_p, mask_p);  // 4
    deform_kernel<<<rowGrid, 256, DF_SMEM_BYTES>>>(xc1, dw[1][4], dw[1][5], xc0); // 5 <- ncu

    conv_off_kernel<<<rowGrid, 256>>>(xc0, dw[2][0], dw[2][1],
                                      dw[2][2], dw[2][3], off_p, mask_p);
    deform_kernel<<<rowGrid, 256, DF_SMEM_BYTES>>>(xc0, dw[2][4], dw[2][5], xc1);

    conv_small_kernel<3><<<convGrid, 256>>>(xc1, conv_w, conv_b, xfin_p);

    pool_kernel<<<B_*3, 256>>>(xfin_p);
    ch_kernel<<<1, 64>>>(ch_w1, ch_b1, ch_w2, ch_b2);
    ddf_kernel<<<rowGrid, 256>>>(sp_w, sp_b, out_main);
}

// round 12
// speedup vs baseline: 2.1756x; 1.1499x over previous
#include <cuda_runtime.h>
#include <math.h>

#define HW   16384
#define B_   4
#define NCH  67

// ---------------- scratch ------------------------------------------------------
__device__ float g_xcat0[B_*NCH*HW];
__device__ float g_xcat1[B_*NCH*HW];
__device__ float g_off  [B_*18*HW];
__device__ float g_mask [B_*9*HW];
__device__ float g_xfin [B_*3*HW];
__device__ float g_ch   [B_*16*27];
__device__ float g_pool [B_*3];

__device__ __forceinline__ float sigm(float v){ return 1.f/(1.f+__expf(-v)); }

// ---- packed fp32x2 helpers ----------------------------------------------------
typedef unsigned long long ull;
__device__ __forceinline__ ull dup2(float v){
    ull r; asm("mov.b64 %0, {%1, %1};" : "=l"(r) : "f"(v)); return r;
}
__device__ __forceinline__ void ffma2(ull &d, ull a, ull b){
    asm("fma.rn.f32x2 %0, %1, %2, %0;" : "+l"(d) : "l"(a), "l"(b));
}
__device__ __forceinline__ ull add2(ull a, ull b){
    ull r; asm("add.rn.f32x2 %0, %1, %2;" : "=l"(r) : "l"(a), "l"(b)); return r;
}
__device__ __forceinline__ float2 unpk(ull v){
    float2 f; asm("mov.b64 {%0, %1}, %2;" : "=f"(f.x), "=f"(f.y) : "l"(v)); return f;
}

// ---------------- 0) copy LR into both xcat buffers (also shifts ncu index) ---
__global__ void copy_lr_kernel(const float* __restrict__ X)
{
    int i = blockIdx.x*256 + threadIdx.x;          // over B*3*HW/4 float4s
    if (i >= B_*3*HW/4) return;
    int b = i / (3*HW/4), rem = i - b*(3*HW/4);
    float4 v = ((const float4*)X)[i];
    ((float4*)(g_xcat0 + (b*NCH + 64)*HW))[rem] = v;
    ((float4*)(g_xcat1 + (b*NCH + 64)*HW))[rem] = v;
}

// ---------------- 1) ConvLSTM: row-CTA, smem-staged, f32x2 k-pairs ------------
__global__ __launch_bounds__(256) void lstm_kernel(
    const float* __restrict__ X, const float* __restrict__ w,
    const float* __restrict__ bias,
    float* __restrict__ hid, float* __restrict__ cell, float* __restrict__ xcat)
{
    __shared__ float sX[9*132];
    __shared__ float2 sW2[32*3*28];
    __shared__ float2 sB2[32*3];

    int tid = threadIdx.x;
    int b = blockIdx.y, y = blockIdx.x;

    for (int i = tid; i < 2688; i += 256) {
        int kp = i / 84, rem = i - kp*84;
        int g = rem / 28, t = rem - g*28;
        int gbase = (g == 0) ? 0 : (g == 1) ? 128 : 192;
        float v0 = 0.f, v1 = 0.f;
        if (t < 27) {
            v0 = w[(gbase + 2*kp    )*603 + t];
            v1 = w[(gbase + 2*kp + 1)*603 + t];
        }
        sW2[i] = make_float2(v0, v1);
    }
    if (tid < 96) {
        int kp = tid / 3, g = tid - kp*3;
        int gbase = (g == 0) ? 0 : (g == 1) ? 128 : 192;
        sB2[tid] = make_float2(bias[gbase + 2*kp], bias[gbase + 2*kp + 1]);
    }
    if (tid < 9) {
        float* row = sX + tid*132;
        row[0] = 0.f; row[129] = 0.f; row[130] = 0.f; row[131] = 0.f;
    }
    for (int idx = tid; idx < 288; idx += 256) {
        int row9 = idx >> 5, q = idx & 31;
        int c = row9 / 3, r = row9 - c*3;
        int gy = y - 1 + r;
        float4 v = make_float4(0.f, 0.f, 0.f, 0.f);
        if (gy >= 0 && gy < 128)
            v = *(const float4*)(X + (b*3 + c)*HW + gy*128 + q*4);
        float* dst = sX + row9*132 + 1 + q*4;
        dst[0] = v.x; dst[1] = v.y; dst[2] = v.z; dst[3] = v.w;
    }
    __syncthreads();

    int px = tid & 127, kh = tid >> 7;

    ull win[28];
    #pragma unroll
    for (int c = 0; c < 3; c++)
        #pragma unroll
        for (int r = 0; r < 3; r++)
            #pragma unroll
            for (int q = 0; q < 3; q++)
                win[c*9 + r*3 + q] = dup2(sX[(c*3 + r)*132 + px + q]);
    win[27] = 0ull;

    int pix = y*128 + px;
    int kp0 = kh*16;
    #pragma unroll 1
    for (int kp = kp0; kp < kp0 + 16; kp++) {
        ull aI = *(const ull*)&sB2[kp*3 + 0];
        ull aO = *(const ull*)&sB2[kp*3 + 1];
        ull aG = *(const ull*)&sB2[kp*3 + 2];
        const ulonglong2* wI = (const ulonglong2*)(sW2 + (kp*3 + 0)*28);
        const ulonglong2* wO = (const ulonglong2*)(sW2 + (kp*3 + 1)*28);
        const ulonglong2* wG = (const ulonglong2*)(sW2 + (kp*3 + 2)*28);
        #pragma unroll
        for (int t2 = 0; t2 < 14; t2++) {
            ulonglong2 wi = wI[t2];
            ffma2(aI, wi.x, win[2*t2]); ffma2(aI, wi.y, win[2*t2 + 1]);
            ulonglong2 wo = wO[t2];
            ffma2(aO, wo.x, win[2*t2]); ffma2(aO, wo.y, win[2*t2 + 1]);
            ulonglong2 wg = wG[t2];
            ffma2(aG, wg.x, win[2*t2]); ffma2(aG, wg.y, win[2*t2 + 1]);
        }
        float2 ai = unpk(aI), ao = unpk(aO), ag = unpk(aG);
        float c0 = sigm(ai.x)*tanhf(ag.x);
        float c1 = sigm(ai.y)*tanhf(ag.y);
        float h0 = sigm(ao.x)*tanhf(c0);
        float h1 = sigm(ao.y)*tanhf(c1);
        int k0 = 2*kp;
        hid [(b*64 + k0    )*HW + pix] = h0;
        hid [(b*64 + k0 + 1)*HW + pix] = h1;
        cell[(b*64 + k0    )*HW + pix] = c0;
        cell[(b*64 + k0 + 1)*HW + pix] = c1;
        xcat[(b*NCH + k0    )*HW + pix] = h0;
        xcat[(b*NCH + k0 + 1)*HW + pix] = h1;
    }
}

// ---------------- 2) offset/mask conv, f32x2 packed GEMM ----------------------
__global__ __launch_bounds__(256) void conv_off_kernel(
    const float* __restrict__ xcat,
    const float* __restrict__ w0, const float* __restrict__ b0,
    const float* __restrict__ w1, const float* __restrict__ b1,
    float* __restrict__ out0, float* __restrict__ out1)
{
    __shared__ float sTile[16*3*132];
    __shared__ float sW[144*32];

    int tid = threadIdx.x;
    int pg = tid & 31;
    int og = tid >> 5;
    int b = blockIdx.y, y = blockIdx.x;
    int y0 = y - 1;

    ull acc[2][4];
    #pragma unroll
    for (int q = 0; q < 2; q++)
        #pragma unroll
        for (int p = 0; p < 4; p++) acc[q][p] = 0ull;

    for (int c0 = 0; c0 < 67; c0 += 16) {
        int cnt = (67 - c0) < 16 ? (67 - c0) : 16;
        for (int i = tid; i < cnt*3; i += 256) {
            int c = i / 3, r = i - c*3;
            float* row = sTile + c*396 + r*132;
            row[0] = 0.f; row[129] = 0.f; row[130] = 0.f; row[131] = 0.f;
        }
        for (int i = tid; i < cnt*96; i += 256) {
            int c = i / 96, rem = i - c*96;
            int r = rem >> 5, q = rem & 31;
            int gy = y0 + r;
            const float* src = xcat + (b*NCH + c0 + c)*HW;
            float4 v = make_float4(0.f, 0.f, 0.f, 0.f);
            if (gy >= 0 && gy < 128) v = *(const float4*)(src + gy*128 + q*4);
            float* dst = sTile + c*396 + r*132 + 1 + q*4;
            dst[0] = v.x; dst[1] = v.y; dst[2] = v.z; dst[3] = v.w;
        }
        int c09 = c0*9;
        for (int i = tid; i < cnt*288; i += 256) {
            int o = i & 31, tdx = i >> 5;
            float wv = 0.f;
            if (o < 18)      wv = w0[o*603 + c09 + tdx];
            else if (o < 27) wv = w1[(o-18)*603 + c09 + tdx];
            sW[tdx*32 + o] = wv;
        }
        __syncthreads();

        for (int c = 0; c < cnt; c++) {
            #pragma unroll
            for (int ky = 0; ky < 3; ky++) {
                const float* rb = sTile + c*396 + ky*132 + pg*4;
                float4 a4 = *(const float4*)rb;
                float2 a2 = *(const float2*)(rb + 4);
                ull vv[6];
                vv[0] = dup2(a4.x); vv[1] = dup2(a4.y); vv[2] = dup2(a4.z);
                vv[3] = dup2(a4.w); vv[4] = dup2(a2.x); vv[5] = dup2(a2.y);
                #pragma unroll
                for (int kx = 0; kx < 3; kx++) {
                    ulonglong2 w = *(const ulonglong2*)(sW + (c*9 + ky*3 + kx)*32 + og*4);
                    #pragma unroll
                    for (int p = 0; p < 4; p++) {
                        ffma2(acc[0][p], w.x, vv[kx + p]);
                        ffma2(acc[1][p], w.y, vv[kx + p]);
                    }
                }
            }
        }
        __syncthreads();
    }

    int pixb = y*128 + pg*4;
    #pragma unroll
    for (int wp = 0; wp < 2; wp++) {
        int o0 = og*4 + 2*wp;
        float2 a0 = unpk(acc[wp][0]), a1 = unpk(acc[wp][1]);
        float2 a2 = unpk(acc[wp][2]), a3 = unpk(acc[wp][3]);
        if (o0 < 18) {
            float bb = b0[o0];
            *(float4*)(out0 + (b*18 + o0)*HW + pixb) =
                make_float4(a0.x+bb, a1.x+bb, a2.x+bb, a3.x+bb);
        } else if (o0 < 27) {
            float bb = b1[o0-18];
            *(float4*)(out1 + (b*9 + (o0-18))*HW + pixb) =
                make_float4(2.f*sigm(a0.x+bb), 2.f*sigm(a1.x+bb),
                            2.f*sigm(a2.x+bb), 2.f*sigm(a3.x+bb));
        }
        int o1 = o0 + 1;
        if (o1 < 18) {
            float bb = b0[o1];
            *(float4*)(out0 + (b*18 + o1)*HW + pixb) =
                make_float4(a0.y+bb, a1.y+bb, a2.y+bb, a3.y+bb);
        } else if (o1 < 27) {
            float bb = b1[o1-18];
            *(float4*)(out1 + (b*9 + (o1-18))*HW + pixb) =
                make_float4(2.f*sigm(a0.y+bb), 2.f*sigm(a1.y+bb),
                            2.f*sigm(a2.y+bb), 2.f*sigm(a3.y+bb));
        }
    }
}

// ---------------- 2b) small direct conv (final 3-out fuse conv) ---------------
template<int COUT>
__global__ __launch_bounds__(256) void conv_small_kernel(
    const float* __restrict__ xcat,
    const float* __restrict__ w0, const float* __restrict__ b0,
    float* __restrict__ out0)
{
    __shared__ float sT[16*10*34];
    __shared__ float sW[COUT*16*9];
    int tid = threadIdx.x;
    int tx = tid & 31, ty = tid >> 5;
    int b = blockIdx.z;
    int x = blockIdx.x*32 + tx, y = blockIdx.y*8 + ty;
    int gx0 = blockIdx.x*32 - 1, gy0 = blockIdx.y*8 - 1;

    float acc[COUT];
    #pragma unroll
    for (int o = 0; o < COUT; o++) acc[o] = 0.f;

    for (int c0 = 0; c0 < 67; c0 += 16) {
        int cnt = (67 - c0) < 16 ? (67 - c0) : 16;
        for (int i = tid; i < cnt*340; i += 256) {
            int c = i / 340, rem = i - c*340;
            int r = rem / 34, col = rem - r*34;
            int gy = gy0 + r, gx = gx0 + col;
            const float* src = xcat + (b*NCH + c0 + c)*HW;
            sT[i] = (gy >= 0 && gy < 128 && gx >= 0 && gx < 128)
                  ? src[gy*128 + gx] : 0.f;
        }
        int wtot = COUT*cnt*9;
        for (int i = tid; i < wtot; i += 256) {
            int o = i / (cnt*9), rem = i - o*(cnt*9);
            sW[o*144 + rem] = w0[o*603 + c0*9 + rem];
        }
        __syncthreads();
        for (int c = 0; c < cnt; c++) {
            float win[9];
            #pragma unroll
            for (int r = 0; r < 3; r++)
                #pragma unroll
                for (int q = 0; q < 3; q++)
                    win[r*3+q] = sT[c*340 + (ty+r)*34 + (tx+q)];
            #pragma unroll
            for (int o = 0; o < COUT; o++) {
                #pragma unroll
                for (int t = 0; t < 9; t++)
                    acc[o] = fmaf(sW[o*144 + c*9 + t], win[t], acc[o]);
            }
        }
        __syncthreads();
    }
    int pix = y*128 + x;
    #pragma unroll
    for (int o = 0; o < COUT; o++)
        out0[(b*COUT + o)*HW + pix] = acc[o] + b0[o];
}

// ---------------- 3) deform: K-chunk 36 (tap-aligned), 4 CTA/SM ---------------
// smem floats: sWt 1152*4 | sIdx 1152 | sV 36*132 | sWc 36*64  (51264 B)
#define DF_SIDX  4608
#define DF_SV    (4608 + 1152)
#define DF_SWC   (DF_SV + 36*132)
#define DF_SMEM_BYTES ((DF_SWC + 36*64) * 4)

__global__ __launch_bounds__(256, 4) void deform_kernel(
    const float* __restrict__ xcat,
    const float* __restrict__ wmain, const float* __restrict__ bias,
    float* __restrict__ out)
{
    extern __shared__ float smem[];
    float4* sWt = (float4*)smem;                 // [k][128 px] corner weights
    int*    sIdx= (int*)(smem + DF_SIDX);
    float*  sV  = smem + DF_SV;                  // [j][px], stride 132, 36 rows
    float*  sWc = smem + DF_SWC;                 // [j][64 outs], 36 rows

    int tid = threadIdx.x;
    int b = blockIdx.y, y = blockIdx.x;

    // ---- Phase A: bilinear meta (9 taps x 128 px) ----
    for (int e = tid; e < 1152; e += 256) {
        int p = e & 127, k = e >> 7;
        int pix = y*128 + p;
        float offy = g_off [(b*18 + 2*k    )*HW + pix];
        float offx = g_off [(b*18 + 2*k + 1)*HW + pix];
        float m    = g_mask[(b*9  + k      )*HW + pix];
        int ky = k / 3, kx = k - ky*3;
        float py = (float)(y + ky - 1) + offy;
        float px = (float)(p + kx - 1) + offx;
        float fy = floorf(py), fx = floorf(px);
        float wy = py - fy,    wx = px - fx;
        int iy = (int)fy, ix = (int)fx;
        bool vy0 = (iy   >= 0 && iy   <= 127);
        bool vy1 = (iy+1 >= 0 && iy+1 <= 127);
        bool vx0 = (ix   >= 0 && ix   <= 127);
        bool vx1 = (ix+1 >= 0 && ix+1 <= 127);
        float4 wv;
        wv.x = (1.f-wy)*(1.f-wx)*m * ((vy0 && vx0) ? 1.f : 0.f);
        wv.y = (1.f-wy)*wx      *m * ((vy0 && vx1) ? 1.f : 0.f);
        wv.z = wy*(1.f-wx)      *m * ((vy1 && vx0) ? 1.f : 0.f);
        wv.w = wy*wx            *m * ((vy1 && vx1) ? 1.f : 0.f);
        sWt[e] = wv;
        int iy0 = min(max(iy,   0), 127), iy1 = min(max(iy+1, 0), 127);
        int ix0 = min(max(ix,   0), 127), ix1 = min(max(ix+1, 0), 127);
        sIdx[e] = iy0 | (iy1 << 8) | (ix0 << 16) | (ix1 << 24);
    }
    __syncthreads();

    const float* xb = xcat + b*NCH*HW;
    int pg = tid & 31, og = tid >> 5;

    ull acc[4][4];
    #pragma unroll
    for (int q = 0; q < 4; q++)
        #pragma unroll
        for (int p = 0; p < 4; p++) acc[q][p] = 0ull;

    for (int c0 = 0; c0 < 603; c0 += 36) {       // chunks tap-aligned (36 = 4*9)
        int cnt = (603 - c0) < 36 ? (603 - c0) : 36;   // 36 ... then 27
        int nch = cnt / 9;                                // 4 or 3
        // stage weight chunk transposed (pad j>=cnt with 0)
        for (int i = tid; i < 36*64; i += 256) {
            int o = i & 63, j = i >> 6;
            sWc[j*64 + o] = (j < cnt) ? wmain[o*603 + c0 + j] : 0.f;
        }
        // zero sV pad rows (avoid NaN*0 in the padded GEMM lanes)
        if (cnt < 36)
            for (int i = tid; i < (36 - cnt)*132; i += 256)
                sV[cnt*132 + i] = 0.f;
        // group gather: one (tap,pixel) group -> its nch channels in the chunk
        int cbase = (c0/9) * HW;
        for (int g = tid; g < 1152; g += 256) {
            int p = g & 127, k = g >> 7;
            float4 wt = sWt[g];
            int pk = sIdx[g];
            int iy0 =  pk        & 255, iy1 = (pk >> 8)  & 255;
            int ix0 = (pk >> 16) & 255, ix1 = (pk >> 24) & 255;
            int i0 = cbase + iy0*128 + ix0;
            int i1 = cbase + iy0*128 + ix1;
            int i2 = cbase + iy1*128 + ix0;
            int i3 = cbase + iy1*128 + ix1;
            float* sv = sV + k*132 + p;
            #pragma unroll 2
            for (int it = 0; it < nch; it++) {
                float val = wt.x * __ldg(xb + i0) + wt.y * __ldg(xb + i1)
                          + wt.z * __ldg(xb + i2) + wt.w * __ldg(xb + i3);
                *sv = val;
                i0 += HW; i1 += HW; i2 += HW; i3 += HW;
                sv += 9*132;
            }
        }
        __syncthreads();

        const float* vp = sV + pg*4;
        const float* wp_ = sWc + og*8;
        #pragma unroll 4
        for (int j = 0; j < 36; j++) {
            ulonglong2 wA = *(const ulonglong2*)(wp_ + j*64);
            ulonglong2 wB = *(const ulonglong2*)(wp_ + j*64 + 4);
            float4 v = *(const float4*)(vp + j*132);
            ull v0 = dup2(v.x), v1 = dup2(v.y), v2 = dup2(v.z), v3 = dup2(v.w);
            ffma2(acc[0][0], wA.x, v0); ffma2(acc[0][1], wA.x, v1);
            ffma2(acc[0][2], wA.x, v2); ffma2(acc[0][3], wA.x, v3);
            ffma2(acc[1][0], wA.y, v0); ffma2(acc[1][1], wA.y, v1);
            ffma2(acc[1][2], wA.y, v2); ffma2(acc[1][3], wA.y, v3);
            ffma2(acc[2][0], wB.x, v0); ffma2(acc[2][1], wB.x, v1);
            ffma2(acc[2][2], wB.x, v2); ffma2(acc[2][3], wB.x, v3);
            ffma2(acc[3][0], wB.y, v0); ffma2(acc[3][1], wB.y, v1);
            ffma2(acc[3][2], wB.y, v2); ffma2(acc[3][3], wB.y, v3);
        }
        __syncthreads();
    }

    int pixb = y*128 + pg*4;
    #pragma unroll
    for (int wp = 0; wp < 4; wp++) {
        int o0 = og*8 + 2*wp;
        float2 a0 = unpk(acc[wp][0]), a1 = unpk(acc[wp][1]);
        float2 a2 = unpk(acc[wp][2]), a3 = unpk(acc[wp][3]);
        float bb0 = bias[o0], bb1 = bias[o0+1];
        *(float4*)(out + (b*NCH + o0)*HW + pixb) =
            make_float4(a0.x+bb0, a1.x+bb0, a2.x+bb0, a3.x+bb0);
        *(float4*)(out + (b*NCH + o0+1)*HW + pixb) =
            make_float4(a0.y+bb1, a1.y+bb1, a2.y+bb1, a3.y+bb1);
    }
}

// ---------------- 4) global average pool --------------------------------------
__global__ void pool_kernel(const float* __restrict__ xf)
{
    __shared__ float red[256];
    int bc = blockIdx.x, tid = threadIdx.x;
    float s = 0.f;
    const float* p = xf + bc*HW;
    for (int i = tid; i < HW; i += 256) s += p[i];
    red[tid] = s; __syncthreads();
    for (int st = 128; st > 0; st >>= 1) {
        if (tid < st) red[tid] += red[tid + st];
        __syncthreads();
    }
    if (tid == 0) g_pool[bc] = red[0] * (1.f/HW);
}

// ---------------- 5) channel-filter MLP ---------------------------------------
__global__ void ch_kernel(const float* __restrict__ ch_w1, const float* __restrict__ ch_b1,
                          const float* __restrict__ ch_w2, const float* __restrict__ ch_b2)
{
    int t = threadIdx.x;
    if (t >= 64) return;
    int b = t >> 4, s = t & 15;
    float h1[4];
    #pragma unroll
    for (int m = 0; m < 4; m++) {
        float a = ch_b1[s*4 + m];
        #pragma unroll
        for (int c = 0; c < 3; c++) a = fmaf(g_pool[b*3 + c], ch_w1[(s*4 + m)*3 + c], a);
        h1[m] = fmaxf(a, 0.f);
    }
    for (int k = 0; k < 27; k++) {
        float a = ch_b2[s*27 + k];
        #pragma unroll
        for (int m = 0; m < 4; m++) a = fmaf(h1[m], ch_w2[(s*27 + k)*4 + m], a);
        g_ch[(b*16 + s)*27 + k] = a;
    }
}

// ---------------- 6) DDF up: f32x2 s-pair packed, 2 threads/px ----------------
__global__ __launch_bounds__(256) void ddf_kernel(
    const float* __restrict__ spw, const float* __restrict__ spb,
    float* __restrict__ out)
{
    __shared__ __align__(16) float2 sSpw2[8*9*28];
    __shared__ float2 sSpb2[72];
    __shared__ float2 sCh2[216];
    __shared__ float sX[3*3*132];

    int tid = threadIdx.x;
    int b = blockIdx.y, y = blockIdx.x;

    for (int idx = tid; idx < 2016; idx += 256) {
        int i = idx / 252, rem = idx - i*252;
        int k = rem / 28, j = rem - k*28;
        float v0 = 0.f, v1 = 0.f;
        if (j < 27) {
            v0 = spw[((2*i  )*9 + k)*27 + j];
            v1 = spw[((2*i+1)*9 + k)*27 + j];
        }
        sSpw2[idx] = make_float2(v0, v1);
    }
    if (tid < 72) {
        int i = tid / 9, k = tid - i*9;
        sSpb2[tid] = make_float2(spb[(2*i)*9 + k], spb[(2*i+1)*9 + k]);
    }
    if (tid < 216) {
        int i = tid / 27, j = tid - i*27;
        sCh2[tid] = make_float2(g_ch[b*432 + (2*i)*27 + j],
                                g_ch[b*432 + (2*i+1)*27 + j]);
    }
    if (tid < 9) {
        float* row = sX + tid*132;
        row[0] = 0.f; row[129] = 0.f; row[130] = 0.f; row[131] = 0.f;
    }
    for (int idx = tid; idx < 288; idx += 256) {
        int row9 = idx >> 5, q = idx & 31;
        int c = row9 / 3, r = row9 - c*3;
        int gy = y - 1 + r;
        float4 v = make_float4(0.f, 0.f, 0.f, 0.f);
        if (gy >= 0 && gy < 128)
            v = *(const float4*)(g_xfin + (b*3 + c)*HW + gy*128 + q*4);
        float* dst = sX + row9*132 + 1 + q*4;
        dst[0] = v.x; dst[1] = v.y; dst[2] = v.z; dst[3] = v.w;
    }
    __syncthreads();

    int px = tid & 127, half = tid >> 7;

    ull winD[28];
    #pragma unroll
    for (int c = 0; c < 3; c++)
        #pragma unroll
        for (int r = 0; r < 3; r++)
            #pragma unroll
            for (int q = 0; q < 3; q++)
                winD[c*9 + r*3 + q] = dup2(sX[(c*3 + r)*132 + px + q]);
    winD[27] = 0ull;

    float* ob = out + b*3*(512*512);
    int i0 = half*4;
    #pragma unroll 1
    for (int i = i0; i < i0 + 4; i++) {
        ull a0 = 0ull, a1 = 0ull, a2 = 0ull;
        #pragma unroll
        for (int k = 0; k < 9; k++) {
            ull spv = *(const ull*)&sSpb2[i*9 + k];
            const ulonglong2* w2 = (const ulonglong2*)(sSpw2 + (i*9 + k)*28);
            #pragma unroll
            for (int j2 = 0; j2 < 14; j2++) {
                ulonglong2 w = w2[j2];
                ffma2(spv, w.x, winD[j2*2]);
                ffma2(spv, w.y, winD[j2*2 + 1]);
            }
            ull t0 = add2(*(const ull*)&sCh2[i*27 + k],      spv);
            ull t1 = add2(*(const ull*)&sCh2[i*27 + 9 + k],  spv);
            ull t2 = add2(*(const ull*)&sCh2[i*27 + 18 + k], spv);
            ffma2(a0, winD[k],      t0);
            ffma2(a1, winD[9 + k],  t1);
            ffma2(a2, winD[18 + k], t2);
        }
        float2 r0 = unpk(a0), r1 = unpk(a1), r2 = unpk(a2);
        int s0 = 2*i, s1 = 2*i + 1;
        int oy0 = (y << 2) + (s0 >> 2), ox0 = (px << 2) + (s0 & 3);
        int oy1 = (y << 2) + (s1 >> 2), ox1 = (px << 2) + (s1 & 3);
        ob[0*262144 + oy0*512 + ox0] = fminf(fmaxf(r0.x, 0.f), 255.f);
        ob[1*262144 + oy0*512 + ox0] = fminf(fmaxf(r1.x, 0.f), 255.f);
        ob[2*262144 + oy0*512 + ox0] = fminf(fmaxf(r2.x, 0.f), 255.f);
        ob[0*262144 + oy1*512 + ox1] = fminf(fmaxf(r0.y, 0.f), 255.f);
        ob[1*262144 + oy1*512 + ox1] = fminf(fmaxf(r1.y, 0.f), 255.f);
        ob[2*262144 + oy1*512 + ox1] = fminf(fmaxf(r2.y, 0.f), 255.f);
    }
}

// ---------------- host orchestration ------------------------------------------
extern "C" void kernel_launch(void* const* d_in, const int* in_sizes, int n_in,
                              void* d_out, int out_size)
{
    const float* X      = (const float*)d_in[0];
    const float* lstm_w = (const float*)d_in[1];
    const float* lstm_b = (const float*)d_in[2];
    const float* dw[3][6];
    for (int i = 0; i < 3; i++)
        for (int j = 0; j < 6; j++)
            dw[i][j] = (const float*)d_in[3 + i*6 + j];   // ow, ob, mw, mb, w, b
    const float* conv_w = (const float*)d_in[21];
    const float* conv_b = (const float*)d_in[22];
    const float* sp_w   = (const float*)d_in[23];
    const float* sp_b   = (const float*)d_in[24];
    const float* ch_w1  = (const float*)d_in[25];
    const float* ch_b1  = (const float*)d_in[26];
    const float* ch_w2  = (const float*)d_in[27];
    const float* ch_b2  = (const float*)d_in[28];

    float* out_main = (float*)d_out;                     // [4,3,512,512]
    float* hid      = out_main + 4*3*512*512;            // [4,64,128,128]
    float* cell     = hid + 4*64*128*128;                // [4,64,128,128]

    void *pxc0, *pxc1, *poff, *pmask, *pxfin;
    cudaGetSymbolAddress(&pxc0, g_xcat0);
    cudaGetSymbolAddress(&pxc1, g_xcat1);
    cudaGetSymbolAddress(&poff,  g_off);
    cudaGetSymbolAddress(&pmask, g_mask);
    cudaGetSymbolAddress(&pxfin, g_xfin);
    float* xc0 = (float*)pxc0;
    float* xc1 = (float*)pxc1;
    float* off_p  = (float*)poff;
    float* mask_p = (float*)pmask;
    float* xfin_p = (float*)pxfin;

    cudaFuncSetAttribute(deform_kernel, cudaFuncAttributeMaxDynamicSharedMemorySize,
                         DF_SMEM_BYTES);

    dim3 rowGrid(128, B_);
    dim3 convGrid(4, 16, B_);

    copy_lr_kernel<<<(B_*3*HW/4 + 255)/256, 256>>>(X);          // launch 0

    lstm_kernel<<<rowGrid, 256>>>(X, lstm_w, lstm_b, hid, cell, xc0);   // 1

    conv_off_kernel<<<rowGrid, 256>>>(xc0, dw[0][0], dw[0][1],
                                      dw[0][2], dw[0][3], off_p, mask_p);  // 2
    deform_kernel<<<rowGrid, 256, DF_SMEM_BYTES>>>(xc0, dw[0][4], dw[0][5], xc1); // 3

    conv_off_kernel<<<rowGrid, 256>>>(xc1, dw[1][0], dw[1][1],
                                      dw[1][2], dw[1][3], off_p, mask_p);  // 4
    deform_kernel<<<rowGrid, 256, DF_SMEM_BYTES>>>(xc1, dw[1][4], dw[1][5], xc0); // 5 <- ncu

    conv_off_kernel<<<rowGrid, 256>>>(xc0, dw[2][0], dw[2][1],
                                      dw[2][2], dw[2][3], off_p, mask_p);
    deform_kernel<<<rowGrid, 256, DF_SMEM_BYTES>>>(xc0, dw[2][4], dw[2][5], xc1);

    conv_small_kernel<3><<<convGrid, 256>>>(xc1, conv_w, conv_b, xfin_p);

    pool_kernel<<<B_*3, 256>>>(xfin_p);
    ch_kernel<<<1, 64>>>(ch_w1, ch_b1, ch_w2, ch_b2);
    ddf_kernel<<<rowGrid, 256>>>(sp_w, sp_b, out_main);
}

// round 13
// speedup vs baseline: 2.2052x; 1.0136x over previous
#include <cuda_runtime.h>
#include <math.h>

#define HW   16384
#define B_   4
#define NCH  67

// ---------------- scratch ------------------------------------------------------
__device__ float g_xcat0[B_*NCH*HW];
__device__ float g_xcat1[B_*NCH*HW];
__device__ float g_off  [B_*18*HW];
__device__ float g_mask [B_*9*HW];
__device__ float g_xfin [B_*3*HW];
__device__ float g_ch   [B_*16*27];
__device__ float g_pool [B_*3];

__device__ __forceinline__ float sigm(float v){ return 1.f/(1.f+__expf(-v)); }

// ---- packed fp32x2 helpers ----------------------------------------------------
typedef unsigned long long ull;
__device__ __forceinline__ ull dup2(float v){
    ull r; asm("mov.b64 %0, {%1, %1};" : "=l"(r) : "f"(v)); return r;
}
__device__ __forceinline__ void ffma2(ull &d, ull a, ull b){
    asm("fma.rn.f32x2 %0, %1, %2, %0;" : "+l"(d) : "l"(a), "l"(b));
}
__device__ __forceinline__ ull add2(ull a, ull b){
    ull r; asm("add.rn.f32x2 %0, %1, %2;" : "=l"(r) : "l"(a), "l"(b)); return r;
}
__device__ __forceinline__ float2 unpk(ull v){
    float2 f; asm("mov.b64 {%0, %1}, %2;" : "=f"(f.x), "=f"(f.y) : "l"(v)); return f;
}

// ---------------- 0) copy LR into both xcat buffers (also shifts ncu index) ---
__global__ void copy_lr_kernel(const float* __restrict__ X)
{
    int i = blockIdx.x*256 + threadIdx.x;
    if (i >= B_*3*HW/4) return;
    int b = i / (3*HW/4), rem = i - b*(3*HW/4);
    float4 v = ((const float4*)X)[i];
    ((float4*)(g_xcat0 + (b*NCH + 64)*HW))[rem] = v;
    ((float4*)(g_xcat1 + (b*NCH + 64)*HW))[rem] = v;
}

// ---------------- 1) ConvLSTM: row-CTA, smem-staged, f32x2 k-pairs ------------
__global__ __launch_bounds__(256) void lstm_kernel(
    const float* __restrict__ X, const float* __restrict__ w,
    const float* __restrict__ bias,
    float* __restrict__ hid, float* __restrict__ cell, float* __restrict__ xcat)
{
    __shared__ float sX[9*132];
    __shared__ float2 sW2[32*3*28];
    __shared__ float2 sB2[32*3];

    int tid = threadIdx.x;
    int b = blockIdx.y, y = blockIdx.x;

    for (int i = tid; i < 2688; i += 256) {
        int kp = i / 84, rem = i - kp*84;
        int g = rem / 28, t = rem - g*28;
        int gbase = (g == 0) ? 0 : (g == 1) ? 128 : 192;
        float v0 = 0.f, v1 = 0.f;
        if (t < 27) {
            v0 = w[(gbase + 2*kp    )*603 + t];
            v1 = w[(gbase + 2*kp + 1)*603 + t];
        }
        sW2[i] = make_float2(v0, v1);
    }
    if (tid < 96) {
        int kp = tid / 3, g = tid - kp*3;
        int gbase = (g == 0) ? 0 : (g == 1) ? 128 : 192;
        sB2[tid] = make_float2(bias[gbase + 2*kp], bias[gbase + 2*kp + 1]);
    }
    if (tid < 9) {
        float* row = sX + tid*132;
        row[0] = 0.f; row[129] = 0.f; row[130] = 0.f; row[131] = 0.f;
    }
    for (int idx = tid; idx < 288; idx += 256) {
        int row9 = idx >> 5, q = idx & 31;
        int c = row9 / 3, r = row9 - c*3;
        int gy = y - 1 + r;
        float4 v = make_float4(0.f, 0.f, 0.f, 0.f);
        if (gy >= 0 && gy < 128)
            v = *(const float4*)(X + (b*3 + c)*HW + gy*128 + q*4);
        float* dst = sX + row9*132 + 1 + q*4;
        dst[0] = v.x; dst[1] = v.y; dst[2] = v.z; dst[3] = v.w;
    }
    __syncthreads();

    int px = tid & 127, kh = tid >> 7;

    ull win[28];
    #pragma unroll
    for (int c = 0; c < 3; c++)
        #pragma unroll
        for (int r = 0; r < 3; r++)
            #pragma unroll
            for (int q = 0; q < 3; q++)
                win[c*9 + r*3 + q] = dup2(sX[(c*3 + r)*132 + px + q]);
    win[27] = 0ull;

    int pix = y*128 + px;
    int kp0 = kh*16;
    #pragma unroll 1
    for (int kp = kp0; kp < kp0 + 16; kp++) {
        ull aI = *(const ull*)&sB2[kp*3 + 0];
        ull aO = *(const ull*)&sB2[kp*3 + 1];
        ull aG = *(const ull*)&sB2[kp*3 + 2];
        const ulonglong2* wI = (const ulonglong2*)(sW2 + (kp*3 + 0)*28);
        const ulonglong2* wO = (const ulonglong2*)(sW2 + (kp*3 + 1)*28);
        const ulonglong2* wG = (const ulonglong2*)(sW2 + (kp*3 + 2)*28);
        #pragma unroll
        for (int t2 = 0; t2 < 14; t2++) {
            ulonglong2 wi = wI[t2];
            ffma2(aI, wi.x, win[2*t2]); ffma2(aI, wi.y, win[2*t2 + 1]);
            ulonglong2 wo = wO[t2];
            ffma2(aO, wo.x, win[2*t2]); ffma2(aO, wo.y, win[2*t2 + 1]);
            ulonglong2 wg = wG[t2];
            ffma2(aG, wg.x, win[2*t2]); ffma2(aG, wg.y, win[2*t2 + 1]);
        }
        float2 ai = unpk(aI), ao = unpk(aO), ag = unpk(aG);
        float c0 = sigm(ai.x)*tanhf(ag.x);
        float c1 = sigm(ai.y)*tanhf(ag.y);
        float h0 = sigm(ao.x)*tanhf(c0);
        float h1 = sigm(ao.y)*tanhf(c1);
        int k0 = 2*kp;
        hid [(b*64 + k0    )*HW + pix] = h0;
        hid [(b*64 + k0 + 1)*HW + pix] = h1;
        cell[(b*64 + k0    )*HW + pix] = c0;
        cell[(b*64 + k0 + 1)*HW + pix] = c1;
        xcat[(b*NCH + k0    )*HW + pix] = h0;
        xcat[(b*NCH + k0 + 1)*HW + pix] = h1;
    }
}

// ---------------- 2) offset/mask conv, f32x2 packed GEMM ----------------------
__global__ __launch_bounds__(256) void conv_off_kernel(
    const float* __restrict__ xcat,
    const float* __restrict__ w0, const float* __restrict__ b0,
    const float* __restrict__ w1, const float* __restrict__ b1,
    float* __restrict__ out0, float* __restrict__ out1)
{
    __shared__ float sTile[16*3*132];
    __shared__ float sW[144*32];

    int tid = threadIdx.x;
    int pg = tid & 31;
    int og = tid >> 5;
    int b = blockIdx.y, y = blockIdx.x;
    int y0 = y - 1;

    ull acc[2][4];
    #pragma unroll
    for (int q = 0; q < 2; q++)
        #pragma unroll
        for (int p = 0; p < 4; p++) acc[q][p] = 0ull;

    for (int c0 = 0; c0 < 67; c0 += 16) {
        int cnt = (67 - c0) < 16 ? (67 - c0) : 16;
        for (int i = tid; i < cnt*3; i += 256) {
            int c = i / 3, r = i - c*3;
            float* row = sTile + c*396 + r*132;
            row[0] = 0.f; row[129] = 0.f; row[130] = 0.f; row[131] = 0.f;
        }
        for (int i = tid; i < cnt*96; i += 256) {
            int c = i / 96, rem = i - c*96;
            int r = rem >> 5, q = rem & 31;
            int gy = y0 + r;
            const float* src = xcat + (b*NCH + c0 + c)*HW;
            float4 v = make_float4(0.f, 0.f, 0.f, 0.f);
            if (gy >= 0 && gy < 128) v = *(const float4*)(src + gy*128 + q*4);
            float* dst = sTile + c*396 + r*132 + 1 + q*4;
            dst[0] = v.x; dst[1] = v.y; dst[2] = v.z; dst[3] = v.w;
        }
        int c09 = c0*9;
        for (int i = tid; i < cnt*288; i += 256) {
            int o = i & 31, tdx = i >> 5;
            float wv = 0.f;
            if (o < 18)      wv = w0[o*603 + c09 + tdx];
            else if (o < 27) wv = w1[(o-18)*603 + c09 + tdx];
            sW[tdx*32 + o] = wv;
        }
        __syncthreads();

        for (int c = 0; c < cnt; c++) {
            #pragma unroll
            for (int ky = 0; ky < 3; ky++) {
                const float* rb = sTile + c*396 + ky*132 + pg*4;
                float4 a4 = *(const float4*)rb;
                float2 a2 = *(const float2*)(rb + 4);
                ull vv[6];
                vv[0] = dup2(a4.x); vv[1] = dup2(a4.y); vv[2] = dup2(a4.z);
                vv[3] = dup2(a4.w); vv[4] = dup2(a2.x); vv[5] = dup2(a2.y);
                #pragma unroll
                for (int kx = 0; kx < 3; kx++) {
                    ulonglong2 w = *(const ulonglong2*)(sW + (c*9 + ky*3 + kx)*32 + og*4);
                    #pragma unroll
                    for (int p = 0; p < 4; p++) {
                        ffma2(acc[0][p], w.x, vv[kx + p]);
                        ffma2(acc[1][p], w.y, vv[kx + p]);
                    }
                }
            }
        }
        __syncthreads();
    }

    int pixb = y*128 + pg*4;
    #pragma unroll
    for (int wp = 0; wp < 2; wp++) {
        int o0 = og*4 + 2*wp;
        float2 a0 = unpk(acc[wp][0]), a1 = unpk(acc[wp][1]);
        float2 a2 = unpk(acc[wp][2]), a3 = unpk(acc[wp][3]);
        if (o0 < 18) {
            float bb = b0[o0];
            *(float4*)(out0 + (b*18 + o0)*HW + pixb) =
                make_float4(a0.x+bb, a1.x+bb, a2.x+bb, a3.x+bb);
        } else if (o0 < 27) {
            float bb = b1[o0-18];
            *(float4*)(out1 + (b*9 + (o0-18))*HW + pixb) =
                make_float4(2.f*sigm(a0.x+bb), 2.f*sigm(a1.x+bb),
                            2.f*sigm(a2.x+bb), 2.f*sigm(a3.x+bb));
        }
        int o1 = o0 + 1;
        if (o1 < 18) {
            float bb = b0[o1];
            *(float4*)(out0 + (b*18 + o1)*HW + pixb) =
                make_float4(a0.y+bb, a1.y+bb, a2.y+bb, a3.y+bb);
        } else if (o1 < 27) {
            float bb = b1[o1-18];
            *(float4*)(out1 + (b*9 + (o1-18))*HW + pixb) =
                make_float4(2.f*sigm(a0.y+bb), 2.f*sigm(a1.y+bb),
                            2.f*sigm(a2.y+bb), 2.f*sigm(a3.y+bb));
        }
    }
}

// ---------------- 2b) small direct conv (final 3-out fuse conv) ---------------
template<int COUT>
__global__ __launch_bounds__(256) void conv_small_kernel(
    const float* __restrict__ xcat,
    const float* __restrict__ w0, const float* __restrict__ b0,
    float* __restrict__ out0)
{
    __shared__ float sT[16*10*34];
    __shared__ float sW[COUT*16*9];
    int tid = threadIdx.x;
    int tx = tid & 31, ty = tid >> 5;
    int b = blockIdx.z;
    int x = blockIdx.x*32 + tx, y = blockIdx.y*8 + ty;
    int gx0 = blockIdx.x*32 - 1, gy0 = blockIdx.y*8 - 1;

    float acc[COUT];
    #pragma unroll
    for (int o = 0; o < COUT; o++) acc[o] = 0.f;

    for (int c0 = 0; c0 < 67; c0 += 16) {
        int cnt = (67 - c0) < 16 ? (67 - c0) : 16;
        for (int i = tid; i < cnt*340; i += 256) {
            int c = i / 340, rem = i - c*340;
            int r = rem / 34, col = rem - r*34;
            int gy = gy0 + r, gx = gx0 + col;
            const float* src = xcat + (b*NCH + c0 + c)*HW;
            sT[i] = (gy >= 0 && gy < 128 && gx >= 0 && gx < 128)
                  ? src[gy*128 + gx] : 0.f;
        }
        int wtot = COUT*cnt*9;
        for (int i = tid; i < wtot; i += 256) {
            int o = i / (cnt*9), rem = i - o*(cnt*9);
            sW[o*144 + rem] = w0[o*603 + c0*9 + rem];
        }
        __syncthreads();
        for (int c = 0; c < cnt; c++) {
            float win[9];
            #pragma unroll
            for (int r = 0; r < 3; r++)
                #pragma unroll
                for (int q = 0; q < 3; q++)
                    win[r*3+q] = sT[c*340 + (ty+r)*34 + (tx+q)];
            #pragma unroll
            for (int o = 0; o < COUT; o++) {
                #pragma unroll
                for (int t = 0; t < 9; t++)
                    acc[o] = fmaf(sW[o*144 + c*9 + t], win[t], acc[o]);
            }
        }
        __syncthreads();
    }
    int pix = y*128 + x;
    #pragma unroll
    for (int o = 0; o < COUT; o++)
        out0[(b*COUT + o)*HW + pix] = acc[o] + b0[o];
}

// ---------------- 3) deform: double-buffered chunk-18 pipeline, 4 CTA/SM ------
// smem floats: sWt 4608 | sIdx 1152 | sV[2][18*132] | sWc[2][18*64] = 12816 (51264 B)
#define DF_SIDX   4608
#define DF_SV     (4608 + 1152)
#define SV_STRIDE (18*132)
#define DF_SWC    (DF_SV + 2*SV_STRIDE)
#define SWC_STRIDE (18*64)
#define DF_SMEM_BYTES ((DF_SWC + 2*SWC_STRIDE) * 4)
#define NCHUNK 34

__global__ __launch_bounds__(256, 4) void deform_kernel(
    const float* __restrict__ xcat,
    const float* __restrict__ wmain, const float* __restrict__ bias,
    float* __restrict__ out)
{
    extern __shared__ float smem[];
    float4* sWt = (float4*)smem;
    int*    sIdx= (int*)(smem + DF_SIDX);
    float*  sV  = smem + DF_SV;
    float*  sWc = smem + DF_SWC;

    int tid = threadIdx.x;
    int b = blockIdx.y, y = blockIdx.x;

    // ---- Phase A: bilinear meta (9 taps x 128 px) ----
    for (int e = tid; e < 1152; e += 256) {
        int p = e & 127, k = e >> 7;
        int pix = y*128 + p;
        float offy = g_off [(b*18 + 2*k    )*HW + pix];
        float offx = g_off [(b*18 + 2*k + 1)*HW + pix];
        float m    = g_mask[(b*9  + k      )*HW + pix];
        int ky = k / 3, kx = k - ky*3;
        float py = (float)(y + ky - 1) + offy;
        float px = (float)(p + kx - 1) + offx;
        float fy = floorf(py), fx = floorf(px);
        float wy = py - fy,    wx = px - fx;
        int iy = (int)fy, ix = (int)fx;
        bool vy0 = (iy   >= 0 && iy   <= 127);
        bool vy1 = (iy+1 >= 0 && iy+1 <= 127);
        bool vx0 = (ix   >= 0 && ix   <= 127);
        bool vx1 = (ix+1 >= 0 && ix+1 <= 127);
        float4 wv;
        wv.x = (1.f-wy)*(1.f-wx)*m * ((vy0 && vx0) ? 1.f : 0.f);
        wv.y = (1.f-wy)*wx      *m * ((vy0 && vx1) ? 1.f : 0.f);
        wv.z = wy*(1.f-wx)      *m * ((vy1 && vx0) ? 1.f : 0.f);
        wv.w = wy*wx            *m * ((vy1 && vx1) ? 1.f : 0.f);
        sWt[e] = wv;
        int iy0 = min(max(iy,   0), 127), iy1 = min(max(iy+1, 0), 127);
        int ix0 = min(max(ix,   0), 127), ix1 = min(max(ix+1, 0), 127);
        sIdx[e] = iy0 | (iy1 << 8) | (ix0 << 16) | (ix1 << 24);
    }

    const float* xb = xcat + b*NCH*HW;
    int pg = tid & 31, og = tid >> 5;

    ull acc[4][4];
    #pragma unroll
    for (int q = 0; q < 4; q++)
        #pragma unroll
        for (int p = 0; p < 4; p++) acc[q][p] = 0ull;

    // ---- staging lambda (chunk c into buffer buf) ----
    auto stage = [&](int c, int buf) {
        int c0 = c*18;
        int cnt = (603 - c0) < 18 ? (603 - c0) : 18;    // 18, last chunk 9
        int nch = cnt / 9;                              // 2 or 1
        float* sVb = sV + buf*SV_STRIDE;
        float* sWb = sWc + buf*SWC_STRIDE;
        for (int i = tid; i < 18*64; i += 256) {
            int o = i & 63, j = i >> 6;
            sWb[j*64 + o] = (j < cnt) ? wmain[o*603 + c0 + j] : 0.f;
        }
        if (cnt < 18)
            for (int i = tid; i < (18 - cnt)*132; i += 256)
                sVb[cnt*132 + i] = 0.f;
        int cbase = (c0/9) * HW;
        for (int g = tid; g < 1152; g += 256) {
            int p = g & 127, k = g >> 7;
            float4 wt = sWt[g];
            int pk = sIdx[g];
            int iy0 =  pk        & 255, iy1 = (pk >> 8)  & 255;
            int ix0 = (pk >> 16) & 255, ix1 = (pk >> 24) & 255;
            int i0 = cbase + iy0*128 + ix0;
            int i1 = cbase + iy0*128 + ix1;
            int i2 = cbase + iy1*128 + ix0;
            int i3 = cbase + iy1*128 + ix1;
            float* sv = sVb + k*132 + p;
            if (nch == 2) {
                float a0 = __ldg(xb + i0),      a1 = __ldg(xb + i1);
                float a2 = __ldg(xb + i2),      a3 = __ldg(xb + i3);
                float b0 = __ldg(xb + i0 + HW), b1 = __ldg(xb + i1 + HW);
                float b2 = __ldg(xb + i2 + HW), b3 = __ldg(xb + i3 + HW);
                sv[0]     = wt.x*a0 + wt.y*a1 + wt.z*a2 + wt.w*a3;
                sv[9*132] = wt.x*b0 + wt.y*b1 + wt.z*b2 + wt.w*b3;
            } else {
                float a0 = __ldg(xb + i0), a1 = __ldg(xb + i1);
                float a2 = __ldg(xb + i2), a3 = __ldg(xb + i3);
                sv[0] = wt.x*a0 + wt.y*a1 + wt.z*a2 + wt.w*a3;
            }
        }
    };

    __syncthreads();          // meta ready
    stage(0, 0);
    __syncthreads();          // chunk 0 ready

    for (int c = 0; c < NCHUNK; c++) {
        int buf = c & 1;
        if (c + 1 < NCHUNK) stage(c + 1, buf ^ 1);

        const float* vp = sV + buf*SV_STRIDE + pg*4;
        const float* wp_ = sWc + buf*SWC_STRIDE + og*8;
        #pragma unroll 6
        for (int j = 0; j < 18; j++) {
            ulonglong2 wA = *(const ulonglong2*)(wp_ + j*64);
            ulonglong2 wB = *(const ulonglong2*)(wp_ + j*64 + 4);
            float4 v = *(const float4*)(vp + j*132);
            ull v0 = dup2(v.x), v1 = dup2(v.y), v2 = dup2(v.z), v3 = dup2(v.w);
            ffma2(acc[0][0], wA.x, v0); ffma2(acc[0][1], wA.x, v1);
            ffma2(acc[0][2], wA.x, v2); ffma2(acc[0][3], wA.x, v3);
            ffma2(acc[1][0], wA.y, v0); ffma2(acc[1][1], wA.y, v1);
            ffma2(acc[1][2], wA.y, v2); ffma2(acc[1][3], wA.y, v3);
            ffma2(acc[2][0], wB.x, v0); ffma2(acc[2][1], wB.x, v1);
            ffma2(acc[2][2], wB.x, v2); ffma2(acc[2][3], wB.x, v3);
            ffma2(acc[3][0], wB.y, v0); ffma2(acc[3][1], wB.y, v1);
            ffma2(acc[3][2], wB.y, v2); ffma2(acc[3][3], wB.y, v3);
        }
        __syncthreads();
    }

    int pixb = y*128 + pg*4;
    #pragma unroll
    for (int wp = 0; wp < 4; wp++) {
        int o0 = og*8 + 2*wp;
        float2 a0 = unpk(acc[wp][0]), a1 = unpk(acc[wp][1]);
        float2 a2 = unpk(acc[wp][2]), a3 = unpk(acc[wp][3]);
        float bb0 = bias[o0], bb1 = bias[o0+1];
        *(float4*)(out + (b*NCH + o0)*HW + pixb) =
            make_float4(a0.x+bb0, a1.x+bb0, a2.x+bb0, a3.x+bb0);
        *(float4*)(out + (b*NCH + o0+1)*HW + pixb) =
            make_float4(a0.y+bb1, a1.y+bb1, a2.y+bb1, a3.y+bb1);
    }
}

// ---------------- 4) global average pool --------------------------------------
__global__ void pool_kernel(const float* __restrict__ xf)
{
    __shared__ float red[256];
    int bc = blockIdx.x, tid = threadIdx.x;
    float s = 0.f;
    const float* p = xf + bc*HW;
    for (int i = tid; i < HW; i += 256) s += p[i];
    red[tid] = s; __syncthreads();
    for (int st = 128; st > 0; st >>= 1) {
        if (tid < st) red[tid] += red[tid + st];
        __syncthreads();
    }
    if (tid == 0) g_pool[bc] = red[0] * (1.f/HW);
}

// ---------------- 5) channel-filter MLP ---------------------------------------
__global__ void ch_kernel(const float* __restrict__ ch_w1, const float* __restrict__ ch_b1,
                          const float* __restrict__ ch_w2, const float* __restrict__ ch_b2)
{
    int t = threadIdx.x;
    if (t >= 64) return;
    int b = t >> 4, s = t & 15;
    float h1[4];
    #pragma unroll
    for (int m = 0; m < 4; m++) {
        float a = ch_b1[s*4 + m];
        #pragma unroll
        for (int c = 0; c < 3; c++) a = fmaf(g_pool[b*3 + c], ch_w1[(s*4 + m)*3 + c], a);
        h1[m] = fmaxf(a, 0.f);
    }
    for (int k = 0; k < 27; k++) {
        float a = ch_b2[s*27 + k];
        #pragma unroll
        for (int m = 0; m < 4; m++) a = fmaf(h1[m], ch_w2[(s*27 + k)*4 + m], a);
        g_ch[(b*16 + s)*27 + k] = a;
    }
}

// ---------------- 6) DDF up: f32x2 s-pair packed, 2 threads/px ----------------
__global__ __launch_bounds__(256) void ddf_kernel(
    const float* __restrict__ spw, const float* __restrict__ spb,
    float* __restrict__ out)
{
    __shared__ __align__(16) float2 sSpw2[8*9*28];
    __shared__ float2 sSpb2[72];
    __shared__ float2 sCh2[216];
    __shared__ float sX[3*3*132];

    int tid = threadIdx.x;
    int b = blockIdx.y, y = blockIdx.x;

    for (int idx = tid; idx < 2016; idx += 256) {
        int i = idx / 252, rem = idx - i*252;
        int k = rem / 28, j = rem - k*28;
        float v0 = 0.f, v1 = 0.f;
        if (j < 27) {
            v0 = spw[((2*i  )*9 + k)*27 + j];
            v1 = spw[((2*i+1)*9 + k)*27 + j];
        }
        sSpw2[idx] = make_float2(v0, v1);
    }
    if (tid < 72) {
        int i = tid / 9, k = tid - i*9;
        sSpb2[tid] = make_float2(spb[(2*i)*9 + k], spb[(2*i+1)*9 + k]);
    }
    if (tid < 216) {
        int i = tid / 27, j = tid - i*27;
        sCh2[tid] = make_float2(g_ch[b*432 + (2*i)*27 + j],
                                g_ch[b*432 + (2*i+1)*27 + j]);
    }
    if (tid < 9) {
        float* row = sX + tid*132;
        row[0] = 0.f; row[129] = 0.f; row[130] = 0.f; row[131] = 0.f;
    }
    for (int idx = tid; idx < 288; idx += 256) {
        int row9 = idx >> 5, q = idx & 31;
        int c = row9 / 3, r = row9 - c*3;
        int gy = y - 1 + r;
        float4 v = make_float4(0.f, 0.f, 0.f, 0.f);
        if (gy >= 0 && gy < 128)
            v = *(const float4*)(g_xfin + (b*3 + c)*HW + gy*128 + q*4);
        float* dst = sX + row9*132 + 1 + q*4;
        dst[0] = v.x; dst[1] = v.y; dst[2] = v.z; dst[3] = v.w;
    }
    __syncthreads();

    int px = tid & 127, half = tid >> 7;

    ull winD[28];
    #pragma unroll
    for (int c = 0; c < 3; c++)
        #pragma unroll
        for (int r = 0; r < 3; r++)
            #pragma unroll
            for (int q = 0; q < 3; q++)
                winD[c*9 + r*3 + q] = dup2(sX[(c*3 + r)*132 + px + q]);
    winD[27] = 0ull;

    float* ob = out + b*3*(512*512);
    int i0 = half*4;
    #pragma unroll 1
    for (int i = i0; i < i0 + 4; i++) {
        ull a0 = 0ull, a1 = 0ull, a2 = 0ull;
        #pragma unroll
        for (int k = 0; k < 9; k++) {
            ull spv = *(const ull*)&sSpb2[i*9 + k];
            const ulonglong2* w2 = (const ulonglong2*)(sSpw2 + (i*9 + k)*28);
            #pragma unroll
            for (int j2 = 0; j2 < 14; j2++) {
                ulonglong2 w = w2[j2];
                ffma2(spv, w.x, winD[j2*2]);
                ffma2(spv, w.y, winD[j2*2 + 1]);
            }
            ull t0 = add2(*(const ull*)&sCh2[i*27 + k],      spv);
            ull t1 = add2(*(const ull*)&sCh2[i*27 + 9 + k],  spv);
            ull t2 = add2(*(const ull*)&sCh2[i*27 + 18 + k], spv);
            ffma2(a0, winD[k],      t0);
            ffma2(a1, winD[9 + k],  t1);
            ffma2(a2, winD[18 + k], t2);
        }
        float2 r0 = unpk(a0), r1 = unpk(a1), r2 = unpk(a2);
        int s0 = 2*i, s1 = 2*i + 1;
        int oy0 = (y << 2) + (s0 >> 2), ox0 = (px << 2) + (s0 & 3);
        int oy1 = (y << 2) + (s1 >> 2), ox1 = (px << 2) + (s1 & 3);
        ob[0*262144 + oy0*512 + ox0] = fminf(fmaxf(r0.x, 0.f), 255.f);
        ob[1*262144 + oy0*512 + ox0] = fminf(fmaxf(r1.x, 0.f), 255.f);
        ob[2*262144 + oy0*512 + ox0] = fminf(fmaxf(r2.x, 0.f), 255.f);
        ob[0*262144 + oy1*512 + ox1] = fminf(fmaxf(r0.y, 0.f), 255.f);
        ob[1*262144 + oy1*512 + ox1] = fminf(fmaxf(r1.y, 0.f), 255.f);
        ob[2*262144 + oy1*512 + ox1] = fminf(fmaxf(r2.y, 0.f), 255.f);
    }
}

// ---------------- host orchestration ------------------------------------------
extern "C" void kernel_launch(void* const* d_in, const int* in_sizes, int n_in,
                              void* d_out, int out_size)
{
    const float* X      = (const float*)d_in[0];
    const float* lstm_w = (const float*)d_in[1];
    const float* lstm_b = (const float*)d_in[2];
    const float* dw[3][6];
    for (int i = 0; i < 3; i++)
        for (int j = 0; j < 6; j++)
            dw[i][j] = (const float*)d_in[3 + i*6 + j];   // ow, ob, mw, mb, w, b
    const float* conv_w = (const float*)d_in[21];
    const float* conv_b = (const float*)d_in[22];
    const float* sp_w   = (const float*)d_in[23];
    const float* sp_b   = (const float*)d_in[24];
    const float* ch_w1  = (const float*)d_in[25];
    const float* ch_b1  = (const float*)d_in[26];
    const float* ch_w2  = (const float*)d_in[27];
    const float* ch_b2  = (const float*)d_in[28];

    float* out_main = (float*)d_out;                     // [4,3,512,512]
    float* hid      = out_main + 4*3*512*512;            // [4,64,128,128]
    float* cell     = hid + 4*64*128*128;                // [4,64,128,128]

    void *pxc0, *pxc1, *poff, *pmask, *pxfin;
    cudaGetSymbolAddress(&pxc0, g_xcat0);
    cudaGetSymbolAddress(&pxc1, g_xcat1);
    cudaGetSymbolAddress(&poff,  g_off);
    cudaGetSymbolAddress(&pmask, g_mask);
    cudaGetSymbolAddress(&pxfin, g_xfin);
    float* xc0 = (float*)pxc0;
    float* xc1 = (float*)pxc1;
    float* off_p  = (float*)poff;
    float* mask_p = (float*)pmask;
    float* xfin_p = (float*)pxfin;

    cudaFuncSetAttribute(deform_kernel, cudaFuncAttributeMaxDynamicSharedMemorySize,
                         DF_SMEM_BYTES);

    dim3 rowGrid(128, B_);
    dim3 convGrid(4, 16, B_);

    copy_lr_kernel<<<(B_*3*HW/4 + 255)/256, 256>>>(X);          // launch 0

    lstm_kernel<<<rowGrid, 256>>>(X, lstm_w, lstm_b, hid, cell, xc0);   // 1

    conv_off_kernel<<<rowGrid, 256>>>(xc0, dw[0][0], dw[0][1],
                                      dw[0][2], dw[0][3], off_p, mask_p);  // 2
    deform_kernel<<<rowGrid, 256, DF_SMEM_BYTES>>>(xc0, dw[0][4], dw[0][5], xc1); // 3

    conv_off_kernel<<<rowGrid, 256>>>(xc1, dw[1][0], dw[1][1],
                                      dw[1][2], dw[1][3], off_p, mask_p);  // 4
    deform_kernel<<<rowGrid, 256, DF_SMEM_BYTES>>>(xc1, dw[1][4], dw[1][5], xc0); // 5 <- ncu

    conv_off_kernel<<<rowGrid, 256>>>(xc0, dw[2][0], dw[2][1],
                                      dw[2][2], dw[2][3], off_p, mask_p);
    deform_kernel<<<rowGrid, 256, DF_SMEM_BYTES>>>(xc0, dw[2][4], dw[2][5], xc1);

    conv_small_kernel<3><<<convGrid, 256>>>(xc1, conv_w, conv_b, xfin_p);

    pool_kernel<<<B_*3, 256>>>(xfin_p);
    ch_kernel<<<1, 64>>>(ch_w1, ch_b1, ch_w2, ch_b2);
    ddf_kernel<<<rowGrid, 256>>>(sp_w, sp_b, out_main);
}